// round 1
// baseline (speedup 1.0000x reference)
#include <cuda_runtime.h>
#include <math.h>

// Problem constants
#define T   2048      // B*S tokens
#define Dm  512
#define Np  32
#define Hd  2048
#define Kk  4
#define NHd 8
#define HDd 64
#define Sd  1024
#define Bd  2
#define D3  1536      // 3*Dm

// ---------------- scratch (static device memory; no allocations) ----------------
__device__ int   g_idx[T * Kk];
__device__ int   g_cnt[Np];
__device__ int   g_list[Np * T];
__device__ float g_h[T * Kk * Hd];          // 64 MB  gelu(x@W1) per selected pair
__device__ float g_pairs[T * Kk * Dm];      // 16 MB  per-pair FFN outputs
__device__ float g_nout[T * Dm];            // neuron_out (mean over k)
__device__ float g_qkv[T * D3];
__device__ float g_attno[T * Dm];           // attention head outputs (pre out-proj)
__device__ float g_attnout[T * Dm];         // after out-proj
__device__ float g_WqkvT[Dm * D3];          // [512,1536]
__device__ float g_WoT[Dm * Dm];            // [512,512]

__device__ __forceinline__ float gelu_f(float v) {
    float u = 0.7978845608028654f * (v + 0.044715f * v * v * v);
    return 0.5f * v * (1.0f + tanhf(u));
}

// ---------------- 1. router: top-4 of logits (softmax is monotonic) ----------------
__global__ void router_k(const float* __restrict__ x, const float* __restrict__ Wr,
                         const float* __restrict__ br) {
    int warp = threadIdx.x >> 5, lane = threadIdx.x & 31;
    int t = blockIdx.x * 8 + warp;
    const float* xp = x + (size_t)t * Dm + lane * 16;
    float4 xv[4];
#pragma unroll
    for (int i = 0; i < 4; i++) xv[i] = *(const float4*)(xp + i * 4);
    float lg[32];
#pragma unroll 1
    for (int n = 0; n < 32; n++) {
        const float* wp = Wr + n * Dm + lane * 16;
        float acc = 0.f;
#pragma unroll
        for (int i = 0; i < 4; i++) {
            float4 w = *(const float4*)(wp + i * 4);
            acc += xv[i].x * w.x + xv[i].y * w.y + xv[i].z * w.z + xv[i].w * w.w;
        }
#pragma unroll
        for (int o = 16; o; o >>= 1) acc += __shfl_xor_sync(0xffffffffu, acc, o);
        lg[n] = acc + br[n];
    }
    if (lane == 0) {
        unsigned used = 0;
        for (int k2 = 0; k2 < 4; k2++) {
            float best = -1e30f; int bi = 0;
            for (int n = 0; n < 32; n++)
                if (!((used >> n) & 1u) && lg[n] > best) { best = lg[n]; bi = n; }
            used |= 1u << bi;
            g_idx[t * 4 + k2] = bi;
        }
    }
}

__global__ void zero_k() { if (threadIdx.x < Np) g_cnt[threadIdx.x] = 0; }

__global__ void build_k() {
    int e = blockIdx.x * 256 + threadIdx.x;
    if (e >= T * Kk) return;
    int n = g_idx[e];
    int pos = atomicAdd(&g_cnt[n], 1);   // order irrelevant: each pair writes its own slot
    g_list[n * T + pos] = e;
}

// ---------------- 2. FFN pass 1: h = gelu(x @ W1[n] + b1[n]) ----------------
// grid (16 hchunks, 128 tiles, 32 neurons), 256 thr. Tile = 16 tokens x 128 H-cols.
__global__ void ffn1_k(const float* __restrict__ x, const float* __restrict__ W1,
                       const float* __restrict__ b1) {
    int n = blockIdx.z, tile = blockIdx.y, hc = blockIdx.x;
    int cnt = g_cnt[n];
    int base = tile * 16;
    if (base >= cnt) return;
    __shared__ float xs[16 * Dm];
    __shared__ int es[16];
    int tid = threadIdx.x;
    int rv = min(16, cnt - base);
    if (tid < 16) es[tid] = (tid < rv) ? g_list[n * T + base + tid] : -1;
    __syncthreads();
    for (int f = tid; f < 16 * 128; f += 256) {
        int r = f >> 7, c4 = (f & 127) << 2;
        int e = es[r];
        float4 v = make_float4(0.f, 0.f, 0.f, 0.f);
        if (e >= 0) v = *(const float4*)&x[(size_t)(e >> 2) * Dm + c4];
        *(float4*)&xs[r * Dm + c4] = v;
    }
    __syncthreads();
    int tx = tid & 31, ty = tid >> 5, r0 = ty * 2;
    const float* wp = W1 + (size_t)n * Dm * Hd + hc * 128 + tx * 4;
    float a0[4] = {0.f,0.f,0.f,0.f}, a1[4] = {0.f,0.f,0.f,0.f};
#pragma unroll 4
    for (int d = 0; d < Dm; d++) {
        float4 w = *(const float4*)wp; wp += Hd;
        float x0 = xs[r0 * Dm + d], x1 = xs[r0 * Dm + Dm + d];
        a0[0] += x0 * w.x; a0[1] += x0 * w.y; a0[2] += x0 * w.z; a0[3] += x0 * w.w;
        a1[0] += x1 * w.x; a1[1] += x1 * w.y; a1[2] += x1 * w.z; a1[3] += x1 * w.w;
    }
    int col = hc * 128 + tx * 4;
    float4 bb = *(const float4*)&b1[n * Hd + col];
    int e0 = es[r0], e1 = es[r0 + 1];
    if (e0 >= 0) {
        float4 o;
        o.x = gelu_f(a0[0] + bb.x); o.y = gelu_f(a0[1] + bb.y);
        o.z = gelu_f(a0[2] + bb.z); o.w = gelu_f(a0[3] + bb.w);
        *(float4*)&g_h[(size_t)e0 * Hd + col] = o;
    }
    if (e1 >= 0) {
        float4 o;
        o.x = gelu_f(a1[0] + bb.x); o.y = gelu_f(a1[1] + bb.y);
        o.z = gelu_f(a1[2] + bb.z); o.w = gelu_f(a1[3] + bb.w);
        *(float4*)&g_h[(size_t)e1 * Hd + col] = o;
    }
}

// ---------------- 3. FFN pass 2: out_pair = h @ W2[n] + b2[n] ----------------
// grid (4 dchunks, 128 tiles, 32 neurons), 256 thr. Tile = 16 tokens x 128 D-cols.
__global__ void ffn2_k(const float* __restrict__ W2, const float* __restrict__ b2) {
    int n = blockIdx.z, tile = blockIdx.y, dc = blockIdx.x;
    int cnt = g_cnt[n];
    int base = tile * 16;
    if (base >= cnt) return;
    __shared__ float hs[16 * 64];
    __shared__ int es[16];
    int tid = threadIdx.x;
    int rv = min(16, cnt - base);
    if (tid < 16) es[tid] = (tid < rv) ? g_list[n * T + base + tid] : -1;
    __syncthreads();
    int tx = tid & 31, ty = tid >> 5, r0 = ty * 2;
    int lr = tid >> 4, lj = (tid & 15) << 2;
    const float* wp = W2 + (size_t)n * Hd * Dm + dc * 128 + tx * 4;
    float a0[4] = {0.f,0.f,0.f,0.f}, a1[4] = {0.f,0.f,0.f,0.f};
    int elr = es[lr];
    for (int jb = 0; jb < Hd; jb += 64) {
        __syncthreads();
        float4 hv = make_float4(0.f, 0.f, 0.f, 0.f);
        if (elr >= 0) hv = *(const float4*)&g_h[(size_t)elr * Hd + jb + lj];
        *(float4*)&hs[lr * 64 + lj] = hv;
        __syncthreads();
#pragma unroll 8
        for (int j = 0; j < 64; j++) {
            float4 w = *(const float4*)wp; wp += Dm;
            float h0 = hs[r0 * 64 + j], h1 = hs[r0 * 64 + 64 + j];
            a0[0] += h0 * w.x; a0[1] += h0 * w.y; a0[2] += h0 * w.z; a0[3] += h0 * w.w;
            a1[0] += h1 * w.x; a1[1] += h1 * w.y; a1[2] += h1 * w.z; a1[3] += h1 * w.w;
        }
    }
    int col = dc * 128 + tx * 4;
    float4 bb = *(const float4*)&b2[n * Dm + col];
    int e0 = es[r0], e1 = es[r0 + 1];
    if (e0 >= 0) {
        float4 o = make_float4(a0[0] + bb.x, a0[1] + bb.y, a0[2] + bb.z, a0[3] + bb.w);
        *(float4*)&g_pairs[(size_t)e0 * Dm + col] = o;
    }
    if (e1 >= 0) {
        float4 o = make_float4(a1[0] + bb.x, a1[1] + bb.y, a1[2] + bb.z, a1[3] + bb.w);
        *(float4*)&g_pairs[(size_t)e1 * Dm + col] = o;
    }
}

// ---------------- 4. mean over k ----------------
__global__ void reduce_k() {
    int id = blockIdx.x * 256 + threadIdx.x;
    if (id >= T * Dm / 4) return;
    int t = id >> 7, c4 = (id & 127) << 2;
    float4 s = make_float4(0.f, 0.f, 0.f, 0.f);
#pragma unroll
    for (int k2 = 0; k2 < 4; k2++) {
        float4 v = *(const float4*)&g_pairs[(size_t)(t * 4 + k2) * Dm + c4];
        s.x += v.x; s.y += v.y; s.z += v.z; s.w += v.w;
    }
    s.x *= 0.25f; s.y *= 0.25f; s.z *= 0.25f; s.w *= 0.25f;
    *(float4*)&g_nout[(size_t)t * Dm + c4] = s;
}

// ---------------- 5. weight transpose (W[R,C] -> WT[C,R]) ----------------
__global__ void transpose_k(const float* __restrict__ W, float* __restrict__ WT,
                            int R, int C) {
    __shared__ float tile[32][33];
    int r0 = blockIdx.y * 32, c0 = blockIdx.x * 32;
    int r = r0 + threadIdx.y, c = c0 + threadIdx.x;
#pragma unroll
    for (int i = 0; i < 32; i += 8)
        if (r + i < R && c < C) tile[threadIdx.y + i][threadIdx.x] = W[(size_t)(r + i) * C + c];
    __syncthreads();
    int rt = c0 + threadIdx.y, ct = r0 + threadIdx.x;
#pragma unroll
    for (int i = 0; i < 32; i += 8)
        if (rt + i < C && ct < R) WT[(size_t)(rt + i) * R + ct] = tile[threadIdx.x][threadIdx.y + i];
}

// ---------------- 6. GEMM: C[M,Nc] = A[M,512] @ WT[512,Nc] + bias ----------------
// grid (Nc/128, M/16), 256 thr
__global__ void gemm_k(const float* __restrict__ A, const float* __restrict__ WT,
                       const float* __restrict__ bias, float* __restrict__ C, int Nc) {
    __shared__ float as[16 * Dm];
    int oc = blockIdx.x * 128, m0 = blockIdx.y * 16;
    int tid = threadIdx.x, tx = tid & 31, ty = tid >> 5;
    for (int f = tid; f < 16 * 128; f += 256) {
        int r = f >> 7, c4 = (f & 127) << 2;
        *(float4*)&as[r * Dm + c4] = *(const float4*)&A[(size_t)(m0 + r) * Dm + c4];
    }
    __syncthreads();
    float a0[4] = {0.f,0.f,0.f,0.f}, a1[4] = {0.f,0.f,0.f,0.f};
    const float* wp = WT + oc + tx * 4;
    int r0 = ty * 2;
#pragma unroll 4
    for (int k = 0; k < Dm; k++) {
        float4 w = *(const float4*)wp; wp += Nc;
        float v0 = as[r0 * Dm + k], v1 = as[r0 * Dm + Dm + k];
        a0[0] += v0 * w.x; a0[1] += v0 * w.y; a0[2] += v0 * w.z; a0[3] += v0 * w.w;
        a1[0] += v1 * w.x; a1[1] += v1 * w.y; a1[2] += v1 * w.z; a1[3] += v1 * w.w;
    }
    int col = oc + tx * 4;
    float4 b = *(const float4*)&bias[col];
    float4 o0 = make_float4(a0[0] + b.x, a0[1] + b.y, a0[2] + b.z, a0[3] + b.w);
    float4 o1 = make_float4(a1[0] + b.x, a1[1] + b.y, a1[2] + b.z, a1[3] + b.w);
    *(float4*)&C[(size_t)(m0 + r0) * Nc + col] = o0;
    *(float4*)&C[(size_t)(m0 + r0 + 1) * Nc + col] = o1;
}

// ---------------- 7. attention (one block per (b, h, q-row)) ----------------
__global__ void attn_k() {
    int q = blockIdx.x, h = blockIdx.y, b = blockIdx.z;
    int t = b * Sd + q;
    __shared__ __align__(16) float qv[HDd];
    __shared__ float s[Sd];
    __shared__ float red[4];
    __shared__ float o2[2][HDd];
    int tid = threadIdx.x;  // 128
    if (tid < HDd) qv[tid] = g_qkv[(size_t)t * D3 + h * HDd + tid];
    __syncthreads();
    float lmax = -1e30f;
    for (int j = tid; j < Sd; j += 128) {
        const float* kp = g_qkv + (size_t)(b * Sd + j) * D3 + Dm + h * HDd;
        float acc = 0.f;
#pragma unroll
        for (int i = 0; i < 16; i++) {
            float4 kk = *(const float4*)(kp + i * 4);
            float4 qq = *(const float4*)(qv + i * 4);
            acc += qq.x * kk.x + qq.y * kk.y + qq.z * kk.z + qq.w * kk.w;
        }
        acc *= 0.125f;
        s[j] = acc;
        lmax = fmaxf(lmax, acc);
    }
#pragma unroll
    for (int o = 16; o; o >>= 1) lmax = fmaxf(lmax, __shfl_xor_sync(0xffffffffu, lmax, o));
    if ((tid & 31) == 0) red[tid >> 5] = lmax;
    __syncthreads();
    float bmax = fmaxf(fmaxf(red[0], red[1]), fmaxf(red[2], red[3]));
    float lsum = 0.f;
    for (int j = tid; j < Sd; j += 128) {
        float e = __expf(s[j] - bmax);
        s[j] = e;
        lsum += e;
    }
#pragma unroll
    for (int o = 16; o; o >>= 1) lsum += __shfl_xor_sync(0xffffffffu, lsum, o);
    __syncthreads();
    if ((tid & 31) == 0) red[tid >> 5] = lsum;
    __syncthreads();
    float inv = 1.0f / (red[0] + red[1] + red[2] + red[3]);
    int d = tid & 63, half = tid >> 6;
    const float* vp = g_qkv + (size_t)(b * Sd + half * 512) * D3 + 2 * Dm + h * HDd + d;
    float o = 0.f;
#pragma unroll 4
    for (int j = 0; j < 512; j++) {
        o += s[half * 512 + j] * vp[(size_t)j * D3];
    }
    o2[half][d] = o;
    __syncthreads();
    if (tid < HDd)
        g_attno[(size_t)t * Dm + h * HDd + tid] = (o2[0][tid] + o2[1][tid]) * inv;
}

// ---------------- 8. fused residual + LN1 + residual + LN2 ----------------
__global__ void ln_k(const float* __restrict__ x,
                     const float* __restrict__ ln1w, const float* __restrict__ ln1b,
                     const float* __restrict__ ln2w, const float* __restrict__ ln2b,
                     float* __restrict__ out) {
    int t = blockIdx.x, tid = threadIdx.x;  // 256 threads, 2 elems each
    __shared__ float r1[8], r2[8];
    __shared__ float mu_s, rs_s;
    size_t off = (size_t)t * Dm;
    float a0 = x[off + tid] + g_attnout[off + tid];
    float a1 = x[off + 256 + tid] + g_attnout[off + 256 + tid];
    float s = a0 + a1, ss = a0 * a0 + a1 * a1;
#pragma unroll
    for (int o = 16; o; o >>= 1) {
        s += __shfl_xor_sync(0xffffffffu, s, o);
        ss += __shfl_xor_sync(0xffffffffu, ss, o);
    }
    if ((tid & 31) == 0) { r1[tid >> 5] = s; r2[tid >> 5] = ss; }
    __syncthreads();
    if (tid == 0) {
        float S = 0.f, SS = 0.f;
#pragma unroll
        for (int i = 0; i < 8; i++) { S += r1[i]; SS += r2[i]; }
        float mu = S * (1.0f / 512.0f);
        mu_s = mu;
        rs_s = rsqrtf(SS * (1.0f / 512.0f) - mu * mu + 1e-5f);
    }
    __syncthreads();
    float mu = mu_s, rs = rs_s;
    float z0 = (a0 - mu) * rs * ln1w[tid] + ln1b[tid] + g_nout[off + tid];
    float z1 = (a1 - mu) * rs * ln1w[256 + tid] + ln1b[256 + tid] + g_nout[off + 256 + tid];
    s = z0 + z1; ss = z0 * z0 + z1 * z1;
#pragma unroll
    for (int o = 16; o; o >>= 1) {
        s += __shfl_xor_sync(0xffffffffu, s, o);
        ss += __shfl_xor_sync(0xffffffffu, ss, o);
    }
    __syncthreads();
    if ((tid & 31) == 0) { r1[tid >> 5] = s; r2[tid >> 5] = ss; }
    __syncthreads();
    if (tid == 0) {
        float S = 0.f, SS = 0.f;
#pragma unroll
        for (int i = 0; i < 8; i++) { S += r1[i]; SS += r2[i]; }
        float mu2 = S * (1.0f / 512.0f);
        mu_s = mu2;
        rs_s = rsqrtf(SS * (1.0f / 512.0f) - mu2 * mu2 + 1e-5f);
    }
    __syncthreads();
    mu = mu_s; rs = rs_s;
    out[off + tid] = (z0 - mu) * rs * ln2w[tid] + ln2b[tid];
    out[off + 256 + tid] = (z1 - mu) * rs * ln2w[256 + tid] + ln2b[256 + tid];
}

// ---------------- launcher ----------------
extern "C" void kernel_launch(void* const* d_in, const int* in_sizes, int n_in,
                              void* d_out, int out_size) {
    const float* x    = (const float*)d_in[0];
    const float* Wr   = (const float*)d_in[1];
    const float* br   = (const float*)d_in[2];
    const float* W1   = (const float*)d_in[3];
    const float* b1   = (const float*)d_in[4];
    const float* W2   = (const float*)d_in[5];
    const float* b2   = (const float*)d_in[6];
    const float* Wqkv = (const float*)d_in[7];
    const float* bqkv = (const float*)d_in[8];
    const float* Wo   = (const float*)d_in[9];
    const float* bo   = (const float*)d_in[10];
    const float* ln1w = (const float*)d_in[11];
    const float* ln1b = (const float*)d_in[12];
    const float* ln2w = (const float*)d_in[13];
    const float* ln2b = (const float*)d_in[14];
    float* out = (float*)d_out;

    float *p_nout, *p_qkv, *p_attno, *p_attnout, *p_wqkvt, *p_wot;
    cudaGetSymbolAddress((void**)&p_nout, g_nout);
    cudaGetSymbolAddress((void**)&p_qkv, g_qkv);
    cudaGetSymbolAddress((void**)&p_attno, g_attno);
    cudaGetSymbolAddress((void**)&p_attnout, g_attnout);
    cudaGetSymbolAddress((void**)&p_wqkvt, g_WqkvT);
    cudaGetSymbolAddress((void**)&p_wot, g_WoT);

    // router + list build
    router_k<<<T / 8, 256>>>(x, Wr, br);
    zero_k<<<1, 32>>>();
    build_k<<<(T * Kk + 255) / 256, 256>>>();

    // sparse FFN (only selected neuron-token pairs)
    ffn1_k<<<dim3(16, 128, 32), 256>>>(x, W1, b1);
    ffn2_k<<<dim3(4, 128, 32), 256>>>(W2, b2);
    reduce_k<<<(T * Dm / 4 + 255) / 256, 256>>>();

    // attention
    transpose_k<<<dim3(16, 48), dim3(32, 8)>>>(Wqkv, p_wqkvt, D3, Dm);
    transpose_k<<<dim3(16, 16), dim3(32, 8)>>>(Wo, p_wot, Dm, Dm);
    gemm_k<<<dim3(D3 / 128, T / 16), 256>>>(p_nout, p_wqkvt, bqkv, p_qkv, D3);
    attn_k<<<dim3(Sd, NHd, Bd), 128>>>();
    gemm_k<<<dim3(Dm / 128, T / 16), 256>>>(p_attno, p_wot, bo, p_attnout, Dm);

    // epilogue
    ln_k<<<T, 256>>>(x, ln1w, ln1b, ln2w, ln2b, out);
}

// round 2
// speedup vs baseline: 1.2814x; 1.2814x over previous
#include <cuda_runtime.h>
#include <math.h>

// Problem constants
#define T   2048      // B*S tokens
#define Dm  512
#define Np  32
#define Hd  2048
#define Kk  4
#define NHd 8
#define HDd 64
#define Sd  1024
#define Bd  2
#define D3  1536      // 3*Dm

// smem tile paddings
#define APAD 34       // row length (floats) of duplicated-A tile rows (32 data + 2 pad)
#define BPAD 132      // row length (floats) of B tile rows (128 data + 4 pad)

// ---------------- scratch (static device memory; no allocations) ----------------
__device__ int   g_idx[T * Kk];
__device__ int   g_cnt[Np];
__device__ int   g_list[Np * T];
__device__ float g_h[T * Kk * Hd];          // 64 MB  gelu(x@W1) per selected pair
__device__ float g_pairs[T * Kk * Dm];      // 16 MB  per-pair FFN outputs
__device__ float g_nout[T * Dm];            // neuron_out (mean over k)
__device__ float g_qkv[T * D3];
__device__ float g_attno[T * Dm];           // attention head outputs (pre out-proj)
__device__ float g_attnout[T * Dm];         // after out-proj
__device__ float g_WqkvT[Dm * D3];          // [512,1536]
__device__ float g_WoT[Dm * Dm];            // [512,512]

__device__ __forceinline__ float gelu_f(float v) {
    float u = 0.7978845608028654f * (v + 0.044715f * v * v * v);
    return 0.5f * v * (1.0f + tanhf(u));
}

__device__ __forceinline__ unsigned long long ffma2(unsigned long long a,
                                                    unsigned long long b,
                                                    unsigned long long c) {
    unsigned long long d;
    asm("fma.rn.f32x2 %0, %1, %2, %3;" : "=l"(d) : "l"(a), "l"(b), "l"(c));
    return d;
}

union U2 { unsigned long long u; float2 f; };

// Inner product over a 16-k smem tile: 8 rows x 8 cols per thread, packed f32x2.
__device__ __forceinline__ void mainloop16(const float* __restrict__ as2,
                                           const float* __restrict__ bs,
                                           int m0, int n0,
                                           unsigned long long acc[32]) {
#pragma unroll
    for (int k = 0; k < 16; k++) {
        unsigned long long a[8];
        const float* ab = as2 + (size_t)m0 * APAD + 2 * k;
#pragma unroll
        for (int r = 0; r < 8; r++)
            a[r] = *(const unsigned long long*)(ab + r * APAD);
        const ulonglong2* bp = (const ulonglong2*)(bs + k * BPAD + n0);
        ulonglong2 bA = bp[0];
        ulonglong2 bB = bp[1];
#pragma unroll
        for (int r = 0; r < 8; r++) {
            acc[r * 4 + 0] = ffma2(a[r], bA.x, acc[r * 4 + 0]);
            acc[r * 4 + 1] = ffma2(a[r], bA.y, acc[r * 4 + 1]);
            acc[r * 4 + 2] = ffma2(a[r], bB.x, acc[r * 4 + 2]);
            acc[r * 4 + 3] = ffma2(a[r], bB.y, acc[r * 4 + 3]);
        }
    }
}

// store 8 floats of duplicated A: v -> {v,v}
__device__ __forceinline__ void store_dupA(float* ad, float4 v0, float4 v1) {
    *(float2*)(ad + 0)  = make_float2(v0.x, v0.x);
    *(float2*)(ad + 2)  = make_float2(v0.y, v0.y);
    *(float2*)(ad + 4)  = make_float2(v0.z, v0.z);
    *(float2*)(ad + 6)  = make_float2(v0.w, v0.w);
    *(float2*)(ad + 8)  = make_float2(v1.x, v1.x);
    *(float2*)(ad + 10) = make_float2(v1.y, v1.y);
    *(float2*)(ad + 12) = make_float2(v1.z, v1.z);
    *(float2*)(ad + 14) = make_float2(v1.w, v1.w);
}

// ---------------- 1. router: top-4 of logits (softmax is monotonic) ----------------
__global__ void router_k(const float* __restrict__ x, const float* __restrict__ Wr,
                         const float* __restrict__ br) {
    int warp = threadIdx.x >> 5, lane = threadIdx.x & 31;
    int t = blockIdx.x * 8 + warp;
    const float* xp = x + (size_t)t * Dm + lane * 16;
    float4 xv[4];
#pragma unroll
    for (int i = 0; i < 4; i++) xv[i] = *(const float4*)(xp + i * 4);
    float lg[32];
#pragma unroll 1
    for (int n = 0; n < 32; n++) {
        const float* wp = Wr + n * Dm + lane * 16;
        float acc = 0.f;
#pragma unroll
        for (int i = 0; i < 4; i++) {
            float4 w = *(const float4*)(wp + i * 4);
            acc += xv[i].x * w.x + xv[i].y * w.y + xv[i].z * w.z + xv[i].w * w.w;
        }
#pragma unroll
        for (int o = 16; o; o >>= 1) acc += __shfl_xor_sync(0xffffffffu, acc, o);
        lg[n] = acc + br[n];
    }
    if (lane == 0) {
        unsigned used = 0;
        for (int k2 = 0; k2 < 4; k2++) {
            float best = -1e30f; int bi = 0;
            for (int n = 0; n < 32; n++)
                if (!((used >> n) & 1u) && lg[n] > best) { best = lg[n]; bi = n; }
            used |= 1u << bi;
            g_idx[t * 4 + k2] = bi;
        }
    }
}

__global__ void zero_k() { if (threadIdx.x < Np) g_cnt[threadIdx.x] = 0; }

__global__ void build_k() {
    int e = blockIdx.x * 256 + threadIdx.x;
    if (e >= T * Kk) return;
    int n = g_idx[e];
    int pos = atomicAdd(&g_cnt[n], 1);   // order irrelevant: each pair writes its own slot
    g_list[n * T + pos] = e;
}

// ---------------- 2. FFN pass 1: h = gelu(x @ W1[n] + b1[n]) ----------------
// grid (16 n-chunks, 32 m-tiles, 32 neurons), 128 thr. Tile 64 x 128, K=512.
__global__ __launch_bounds__(128, 3)
void ffn1_k(const float* __restrict__ x, const float* __restrict__ W1,
            const float* __restrict__ b1) {
    int n = blockIdx.z, tile = blockIdx.y, nb = blockIdx.x * 128;
    int cnt = g_cnt[n];
    int base = tile * 64;
    if (base >= cnt) return;
    __shared__ __align__(16) float as2[64 * APAD];
    __shared__ __align__(16) float bs[16 * BPAD];
    __shared__ int es[64];
    int tid = threadIdx.x;
    if (tid < 64) es[tid] = (base + tid < cnt) ? g_list[n * T + base + tid] : -1;
    __syncthreads();

    int tx = tid & 15, ty = tid >> 4;
    int m0 = ty * 8, n0 = tx * 8;
    unsigned long long acc[32];
#pragma unroll
    for (int i = 0; i < 32; i++) acc[i] = 0ull;

    int arow = tid >> 1, ahalf = tid & 1;
    int e_arow = es[arow];
    const float* aptr = (e_arow >= 0) ? (x + (size_t)(e_arow >> 2) * Dm + ahalf * 8) : x;
    float* ad = as2 + (size_t)arow * APAD + ahalf * 16;
    int brow = tid >> 3, bcol = (tid & 7) * 16;
    const float* wbase = W1 + (size_t)n * Dm * Hd + nb + (size_t)brow * Hd + bcol;
    float* bd = bs + brow * BPAD + bcol;

    for (int k0 = 0; k0 < Dm; k0 += 16) {
        float4 av0 = make_float4(0.f, 0.f, 0.f, 0.f), av1 = av0;
        if (e_arow >= 0) { av0 = *(const float4*)(aptr + k0); av1 = *(const float4*)(aptr + k0 + 4); }
        const float* wp = wbase + (size_t)k0 * Hd;
        float4 w0 = *(const float4*)(wp);
        float4 w1 = *(const float4*)(wp + 4);
        float4 w2 = *(const float4*)(wp + 8);
        float4 w3 = *(const float4*)(wp + 12);
        store_dupA(ad, av0, av1);
        *(float4*)(bd + 0) = w0; *(float4*)(bd + 4) = w1;
        *(float4*)(bd + 8) = w2; *(float4*)(bd + 12) = w3;
        __syncthreads();
        mainloop16(as2, bs, m0, n0, acc);
        __syncthreads();
    }

    int col = nb + n0;
    float4 bb0 = *(const float4*)&b1[n * Hd + col];
    float4 bb1 = *(const float4*)&b1[n * Hd + col + 4];
#pragma unroll
    for (int r = 0; r < 8; r++) {
        int e = es[m0 + r];
        if (e < 0) continue;
        U2 p0, p1, p2, p3;
        p0.u = acc[r * 4 + 0]; p1.u = acc[r * 4 + 1];
        p2.u = acc[r * 4 + 2]; p3.u = acc[r * 4 + 3];
        float4 o0, o1;
        o0.x = gelu_f(p0.f.x + bb0.x); o0.y = gelu_f(p0.f.y + bb0.y);
        o0.z = gelu_f(p1.f.x + bb0.z); o0.w = gelu_f(p1.f.y + bb0.w);
        o1.x = gelu_f(p2.f.x + bb1.x); o1.y = gelu_f(p2.f.y + bb1.y);
        o1.z = gelu_f(p3.f.x + bb1.z); o1.w = gelu_f(p3.f.y + bb1.w);
        float* op = &g_h[(size_t)e * Hd + col];
        *(float4*)op = o0;
        *(float4*)(op + 4) = o1;
    }
}

// ---------------- 3. FFN pass 2: out_pair = h @ W2[n] + b2[n] ----------------
// grid (4 n-chunks, 32 m-tiles, 32 neurons), 128 thr. Tile 64 x 128, K=2048.
__global__ __launch_bounds__(128, 3)
void ffn2_k(const float* __restrict__ W2, const float* __restrict__ b2) {
    int n = blockIdx.z, tile = blockIdx.y, nb = blockIdx.x * 128;
    int cnt = g_cnt[n];
    int base = tile * 64;
    if (base >= cnt) return;
    __shared__ __align__(16) float as2[64 * APAD];
    __shared__ __align__(16) float bs[16 * BPAD];
    __shared__ int es[64];
    int tid = threadIdx.x;
    if (tid < 64) es[tid] = (base + tid < cnt) ? g_list[n * T + base + tid] : -1;
    __syncthreads();

    int tx = tid & 15, ty = tid >> 4;
    int m0 = ty * 8, n0 = tx * 8;
    unsigned long long acc[32];
#pragma unroll
    for (int i = 0; i < 32; i++) acc[i] = 0ull;

    int arow = tid >> 1, ahalf = tid & 1;
    int e_arow = es[arow];
    const float* aptr = (e_arow >= 0) ? (g_h + (size_t)e_arow * Hd + ahalf * 8) : g_h;
    float* ad = as2 + (size_t)arow * APAD + ahalf * 16;
    int brow = tid >> 3, bcol = (tid & 7) * 16;
    const float* wbase = W2 + (size_t)n * Hd * Dm + nb + (size_t)brow * Dm + bcol;
    float* bd = bs + brow * BPAD + bcol;

    for (int k0 = 0; k0 < Hd; k0 += 16) {
        float4 av0 = make_float4(0.f, 0.f, 0.f, 0.f), av1 = av0;
        if (e_arow >= 0) { av0 = *(const float4*)(aptr + k0); av1 = *(const float4*)(aptr + k0 + 4); }
        const float* wp = wbase + (size_t)k0 * Dm;
        float4 w0 = *(const float4*)(wp);
        float4 w1 = *(const float4*)(wp + 4);
        float4 w2 = *(const float4*)(wp + 8);
        float4 w3 = *(const float4*)(wp + 12);
        store_dupA(ad, av0, av1);
        *(float4*)(bd + 0) = w0; *(float4*)(bd + 4) = w1;
        *(float4*)(bd + 8) = w2; *(float4*)(bd + 12) = w3;
        __syncthreads();
        mainloop16(as2, bs, m0, n0, acc);
        __syncthreads();
    }

    int col = nb + n0;
    float4 bb0 = *(const float4*)&b2[n * Dm + col];
    float4 bb1 = *(const float4*)&b2[n * Dm + col + 4];
#pragma unroll
    for (int r = 0; r < 8; r++) {
        int e = es[m0 + r];
        if (e < 0) continue;
        U2 p0, p1, p2, p3;
        p0.u = acc[r * 4 + 0]; p1.u = acc[r * 4 + 1];
        p2.u = acc[r * 4 + 2]; p3.u = acc[r * 4 + 3];
        float4 o0 = make_float4(p0.f.x + bb0.x, p0.f.y + bb0.y, p1.f.x + bb0.z, p1.f.y + bb0.w);
        float4 o1 = make_float4(p2.f.x + bb1.x, p2.f.y + bb1.y, p3.f.x + bb1.z, p3.f.y + bb1.w);
        float* op = &g_pairs[(size_t)e * Dm + col];
        *(float4*)op = o0;
        *(float4*)(op + 4) = o1;
    }
}

// ---------------- 4. mean over k ----------------
__global__ void reduce_k() {
    int id = blockIdx.x * 256 + threadIdx.x;
    if (id >= T * Dm / 4) return;
    int t = id >> 7, c4 = (id & 127) << 2;
    float4 s = make_float4(0.f, 0.f, 0.f, 0.f);
#pragma unroll
    for (int k2 = 0; k2 < 4; k2++) {
        float4 v = *(const float4*)&g_pairs[(size_t)(t * 4 + k2) * Dm + c4];
        s.x += v.x; s.y += v.y; s.z += v.z; s.w += v.w;
    }
    s.x *= 0.25f; s.y *= 0.25f; s.z *= 0.25f; s.w *= 0.25f;
    *(float4*)&g_nout[(size_t)t * Dm + c4] = s;
}

// ---------------- 5. weight transpose (W[R,C] -> WT[C,R]) ----------------
__global__ void transpose_k(const float* __restrict__ W, float* __restrict__ WT,
                            int R, int C) {
    __shared__ float tile[32][33];
    int r0 = blockIdx.y * 32, c0 = blockIdx.x * 32;
    int r = r0 + threadIdx.y, c = c0 + threadIdx.x;
#pragma unroll
    for (int i = 0; i < 32; i += 8)
        if (r + i < R && c < C) tile[threadIdx.y + i][threadIdx.x] = W[(size_t)(r + i) * C + c];
    __syncthreads();
    int rt = c0 + threadIdx.y, ct = r0 + threadIdx.x;
#pragma unroll
    for (int i = 0; i < 32; i += 8)
        if (rt + i < C && ct < R) WT[(size_t)(rt + i) * R + ct] = tile[threadIdx.x][threadIdx.y + i];
}

// ---------------- 6. dense GEMM: C[M,Nc] = A[M,512] @ WT[512,Nc] + bias ----------------
// grid (Nc/128, M/64), 128 thr. Tile 64 x 128, K=512.
__global__ __launch_bounds__(128, 3)
void gemm_k(const float* __restrict__ A, const float* __restrict__ WT,
            const float* __restrict__ bias, float* __restrict__ C, int Nc) {
    int nb = blockIdx.x * 128, mg = blockIdx.y * 64;
    __shared__ __align__(16) float as2[64 * APAD];
    __shared__ __align__(16) float bs[16 * BPAD];
    int tid = threadIdx.x;
    int tx = tid & 15, ty = tid >> 4;
    int m0 = ty * 8, n0 = tx * 8;
    unsigned long long acc[32];
#pragma unroll
    for (int i = 0; i < 32; i++) acc[i] = 0ull;

    int arow = tid >> 1, ahalf = tid & 1;
    const float* aptr = A + (size_t)(mg + arow) * Dm + ahalf * 8;
    float* ad = as2 + (size_t)arow * APAD + ahalf * 16;
    int brow = tid >> 3, bcol = (tid & 7) * 16;
    const float* wbase = WT + nb + (size_t)brow * Nc + bcol;
    float* bd = bs + brow * BPAD + bcol;

    for (int k0 = 0; k0 < Dm; k0 += 16) {
        float4 av0 = *(const float4*)(aptr + k0);
        float4 av1 = *(const float4*)(aptr + k0 + 4);
        const float* wp = wbase + (size_t)k0 * Nc;
        float4 w0 = *(const float4*)(wp);
        float4 w1 = *(const float4*)(wp + 4);
        float4 w2 = *(const float4*)(wp + 8);
        float4 w3 = *(const float4*)(wp + 12);
        store_dupA(ad, av0, av1);
        *(float4*)(bd + 0) = w0; *(float4*)(bd + 4) = w1;
        *(float4*)(bd + 8) = w2; *(float4*)(bd + 12) = w3;
        __syncthreads();
        mainloop16(as2, bs, m0, n0, acc);
        __syncthreads();
    }

    int col = nb + n0;
    float4 bb0 = *(const float4*)&bias[col];
    float4 bb1 = *(const float4*)&bias[col + 4];
#pragma unroll
    for (int r = 0; r < 8; r++) {
        U2 p0, p1, p2, p3;
        p0.u = acc[r * 4 + 0]; p1.u = acc[r * 4 + 1];
        p2.u = acc[r * 4 + 2]; p3.u = acc[r * 4 + 3];
        float4 o0 = make_float4(p0.f.x + bb0.x, p0.f.y + bb0.y, p1.f.x + bb0.z, p1.f.y + bb0.w);
        float4 o1 = make_float4(p2.f.x + bb1.x, p2.f.y + bb1.y, p3.f.x + bb1.z, p3.f.y + bb1.w);
        float* op = &C[(size_t)(mg + m0 + r) * Nc + col];
        *(float4*)op = o0;
        *(float4*)(op + 4) = o1;
    }
}

// ---------------- 7. attention (one block per (b, h, q-row)) ----------------
__global__ void attn_k() {
    int q = blockIdx.x, h = blockIdx.y, b = blockIdx.z;
    int t = b * Sd + q;
    __shared__ __align__(16) float qv[HDd];
    __shared__ float s[Sd];
    __shared__ float red[4];
    __shared__ float o2[2][HDd];
    int tid = threadIdx.x;  // 128
    if (tid < HDd) qv[tid] = g_qkv[(size_t)t * D3 + h * HDd + tid];
    __syncthreads();
    float lmax = -1e30f;
    for (int j = tid; j < Sd; j += 128) {
        const float* kp = g_qkv + (size_t)(b * Sd + j) * D3 + Dm + h * HDd;
        float acc = 0.f;
#pragma unroll
        for (int i = 0; i < 16; i++) {
            float4 kk = *(const float4*)(kp + i * 4);
            float4 qq = *(const float4*)(qv + i * 4);
            acc += qq.x * kk.x + qq.y * kk.y + qq.z * kk.z + qq.w * kk.w;
        }
        acc *= 0.125f;
        s[j] = acc;
        lmax = fmaxf(lmax, acc);
    }
#pragma unroll
    for (int o = 16; o; o >>= 1) lmax = fmaxf(lmax, __shfl_xor_sync(0xffffffffu, lmax, o));
    if ((tid & 31) == 0) red[tid >> 5] = lmax;
    __syncthreads();
    float bmax = fmaxf(fmaxf(red[0], red[1]), fmaxf(red[2], red[3]));
    float lsum = 0.f;
    for (int j = tid; j < Sd; j += 128) {
        float e = __expf(s[j] - bmax);
        s[j] = e;
        lsum += e;
    }
#pragma unroll
    for (int o = 16; o; o >>= 1) lsum += __shfl_xor_sync(0xffffffffu, lsum, o);
    __syncthreads();
    if ((tid & 31) == 0) red[tid >> 5] = lsum;
    __syncthreads();
    float inv = 1.0f / (red[0] + red[1] + red[2] + red[3]);
    int d = tid & 63, half = tid >> 6;
    const float* vp = g_qkv + (size_t)(b * Sd + half * 512) * D3 + 2 * Dm + h * HDd + d;
    float o = 0.f;
#pragma unroll 4
    for (int j = 0; j < 512; j++) {
        o += s[half * 512 + j] * vp[(size_t)j * D3];
    }
    o2[half][d] = o;
    __syncthreads();
    if (tid < HDd)
        g_attno[(size_t)t * Dm + h * HDd + tid] = (o2[0][tid] + o2[1][tid]) * inv;
}

// ---------------- 8. fused residual + LN1 + residual + LN2 ----------------
__global__ void ln_k(const float* __restrict__ x,
                     const float* __restrict__ ln1w, const float* __restrict__ ln1b,
                     const float* __restrict__ ln2w, const float* __restrict__ ln2b,
                     float* __restrict__ out) {
    int t = blockIdx.x, tid = threadIdx.x;  // 256 threads, 2 elems each
    __shared__ float r1[8], r2[8];
    __shared__ float mu_s, rs_s;
    size_t off = (size_t)t * Dm;
    float a0 = x[off + tid] + g_attnout[off + tid];
    float a1 = x[off + 256 + tid] + g_attnout[off + 256 + tid];
    float s = a0 + a1, ss = a0 * a0 + a1 * a1;
#pragma unroll
    for (int o = 16; o; o >>= 1) {
        s += __shfl_xor_sync(0xffffffffu, s, o);
        ss += __shfl_xor_sync(0xffffffffu, ss, o);
    }
    if ((tid & 31) == 0) { r1[tid >> 5] = s; r2[tid >> 5] = ss; }
    __syncthreads();
    if (tid == 0) {
        float S = 0.f, SS = 0.f;
#pragma unroll
        for (int i = 0; i < 8; i++) { S += r1[i]; SS += r2[i]; }
        float mu = S * (1.0f / 512.0f);
        mu_s = mu;
        rs_s = rsqrtf(SS * (1.0f / 512.0f) - mu * mu + 1e-5f);
    }
    __syncthreads();
    float mu = mu_s, rs = rs_s;
    float z0 = (a0 - mu) * rs * ln1w[tid] + ln1b[tid] + g_nout[off + tid];
    float z1 = (a1 - mu) * rs * ln1w[256 + tid] + ln1b[256 + tid] + g_nout[off + 256 + tid];
    s = z0 + z1; ss = z0 * z0 + z1 * z1;
#pragma unroll
    for (int o = 16; o; o >>= 1) {
        s += __shfl_xor_sync(0xffffffffu, s, o);
        ss += __shfl_xor_sync(0xffffffffu, ss, o);
    }
    __syncthreads();
    if ((tid & 31) == 0) { r1[tid >> 5] = s; r2[tid >> 5] = ss; }
    __syncthreads();
    if (tid == 0) {
        float S = 0.f, SS = 0.f;
#pragma unroll
        for (int i = 0; i < 8; i++) { S += r1[i]; SS += r2[i]; }
        float mu2 = S * (1.0f / 512.0f);
        mu_s = mu2;
        rs_s = rsqrtf(SS * (1.0f / 512.0f) - mu2 * mu2 + 1e-5f);
    }
    __syncthreads();
    mu = mu_s; rs = rs_s;
    out[off + tid] = (z0 - mu) * rs * ln2w[tid] + ln2b[tid];
    out[off + 256 + tid] = (z1 - mu) * rs * ln2w[256 + tid] + ln2b[256 + tid];
}

// ---------------- launcher ----------------
extern "C" void kernel_launch(void* const* d_in, const int* in_sizes, int n_in,
                              void* d_out, int out_size) {
    const float* x    = (const float*)d_in[0];
    const float* Wr   = (const float*)d_in[1];
    const float* br   = (const float*)d_in[2];
    const float* W1   = (const float*)d_in[3];
    const float* b1   = (const float*)d_in[4];
    const float* W2   = (const float*)d_in[5];
    const float* b2   = (const float*)d_in[6];
    const float* Wqkv = (const float*)d_in[7];
    const float* bqkv = (const float*)d_in[8];
    const float* Wo   = (const float*)d_in[9];
    const float* bo   = (const float*)d_in[10];
    const float* ln1w = (const float*)d_in[11];
    const float* ln1b = (const float*)d_in[12];
    const float* ln2w = (const float*)d_in[13];
    const float* ln2b = (const float*)d_in[14];
    float* out = (float*)d_out;

    float *p_nout, *p_qkv, *p_attno, *p_attnout, *p_wqkvt, *p_wot;
    cudaGetSymbolAddress((void**)&p_nout, g_nout);
    cudaGetSymbolAddress((void**)&p_qkv, g_qkv);
    cudaGetSymbolAddress((void**)&p_attno, g_attno);
    cudaGetSymbolAddress((void**)&p_attnout, g_attnout);
    cudaGetSymbolAddress((void**)&p_wqkvt, g_WqkvT);
    cudaGetSymbolAddress((void**)&p_wot, g_WoT);

    // router + list build
    router_k<<<T / 8, 256>>>(x, Wr, br);
    zero_k<<<1, 32>>>();
    build_k<<<(T * Kk + 255) / 256, 256>>>();

    // sparse FFN (only selected neuron-token pairs), tiled GEMMs with FFMA2
    ffn1_k<<<dim3(16, 32, 32), 128>>>(x, W1, b1);
    ffn2_k<<<dim3(4, 32, 32), 128>>>(W2, b2);
    reduce_k<<<(T * Dm / 4 + 255) / 256, 256>>>();

    // attention
    transpose_k<<<dim3(16, 48), dim3(32, 8)>>>(Wqkv, p_wqkvt, D3, Dm);
    transpose_k<<<dim3(16, 16), dim3(32, 8)>>>(Wo, p_wot, Dm, Dm);
    gemm_k<<<dim3(D3 / 128, T / 64), 128>>>(p_nout, p_wqkvt, bqkv, p_qkv, D3);
    attn_k<<<dim3(Sd, NHd, Bd), 128>>>();
    gemm_k<<<dim3(Dm / 128, T / 64), 128>>>(p_attno, p_wot, bo, p_attnout, Dm);

    // epilogue
    ln_k<<<T, 256>>>(x, ln1w, ln1b, ln2w, ln2b, out);
}

// round 3
// speedup vs baseline: 2.2436x; 1.7509x over previous
#include <cuda_runtime.h>
#include <math.h>

// Problem constants
#define T   2048      // B*S tokens
#define Dm  512
#define Np  32
#define Hd  2048
#define Kk  4
#define NHd 8
#define HDd 64
#define Sd  1024
#define Bd  2
#define D3  1536      // 3*Dm

#define RPAD 132            // k-major smem row length (floats): 128 data + 4 pad
#define KTILE_FLOATS (16 * RPAD)

// attention smem layout (dynamic): Qs[64][68], KPs[64][68], Vs[64][68]
#define AT_PAD 68
#define AT_REG (64 * AT_PAD)
#define SMEM_ATTN (3 * AT_REG * 4)

// ---------------- scratch (static device memory; no allocations) ----------------
__device__ int   g_idx[T * Kk];
__device__ int   g_cnt[Np];
__device__ int   g_list[Np * T];
__device__ float g_h[T * Kk * Hd];          // 64 MB  gelu(x@W1) per selected pair
__device__ float g_pairs[T * Kk * Dm];      // 16 MB  per-pair FFN outputs
__device__ float g_nout[T * Dm];            // neuron_out (mean over k)
__device__ float g_qkv[T * D3];
__device__ float g_attno[T * Dm];           // attention head outputs (pre out-proj)
__device__ float g_attnout[T * Dm];         // after out-proj
__device__ float g_WqkvT[Dm * D3];          // [512,1536]
__device__ float g_WoT[Dm * Dm];            // [512,512]

__device__ __forceinline__ float gelu_f(float v) {
    float u = 0.7978845608028654f * (v + 0.044715f * v * v * v);
    return 0.5f * v * (1.0f + tanhf(u));
}

__device__ __forceinline__ unsigned long long ffma2(unsigned long long a,
                                                    unsigned long long b,
                                                    unsigned long long c) {
    unsigned long long d;
    asm("fma.rn.f32x2 %0, %1, %2, %3;" : "=l"(d) : "l"(a), "l"(b), "l"(c));
    return d;
}

union U2 { unsigned long long u; float2 f; };

// Inner product over a 16-k smem tile, k-major layout.
// asd: duplicated A [k][2*m] (rows RPAD floats). bsk: B [k][n] (rows RPAD floats).
__device__ __forceinline__ void mainloop16d(const float* __restrict__ asd,
                                            const float* __restrict__ bsk,
                                            int m0, int n0,
                                            unsigned long long acc[32]) {
#pragma unroll
    for (int k = 0; k < 16; k++) {
        const ulonglong2* apq = (const ulonglong2*)(asd + k * RPAD + 2 * m0);
        ulonglong2 aP0 = apq[0], aP1 = apq[1], aP2 = apq[2], aP3 = apq[3];
        const ulonglong2* bp = (const ulonglong2*)(bsk + k * RPAD + n0);
        ulonglong2 bA = bp[0], bB = bp[1];
        unsigned long long a[8] = {aP0.x, aP0.y, aP1.x, aP1.y,
                                   aP2.x, aP2.y, aP3.x, aP3.y};
#pragma unroll
        for (int r = 0; r < 8; r++) {
            acc[r * 4 + 0] = ffma2(a[r], bA.x, acc[r * 4 + 0]);
            acc[r * 4 + 1] = ffma2(a[r], bA.y, acc[r * 4 + 1]);
            acc[r * 4 + 2] = ffma2(a[r], bB.x, acc[r * 4 + 2]);
            acc[r * 4 + 3] = ffma2(a[r], bB.y, acc[r * 4 + 3]);
        }
    }
}

// store 8 duplicated A values into k-major tile: ad + i*RPAD <- {v,v}
__device__ __forceinline__ void store_dupA_k(float* ad, float4 a0, float4 a1) {
    *(float2*)(ad + 0 * RPAD) = make_float2(a0.x, a0.x);
    *(float2*)(ad + 1 * RPAD) = make_float2(a0.y, a0.y);
    *(float2*)(ad + 2 * RPAD) = make_float2(a0.z, a0.z);
    *(float2*)(ad + 3 * RPAD) = make_float2(a0.w, a0.w);
    *(float2*)(ad + 4 * RPAD) = make_float2(a1.x, a1.x);
    *(float2*)(ad + 5 * RPAD) = make_float2(a1.y, a1.y);
    *(float2*)(ad + 6 * RPAD) = make_float2(a1.z, a1.z);
    *(float2*)(ad + 7 * RPAD) = make_float2(a1.w, a1.w);
}

__device__ __forceinline__ void store_B_k(float* bd, float4 w0, float4 w1,
                                          float4 w2, float4 w3) {
    *(float4*)(bd + 0) = w0; *(float4*)(bd + 4) = w1;
    *(float4*)(bd + 8) = w2; *(float4*)(bd + 12) = w3;
}

// ---------------- 1. router: top-4 of logits (softmax is monotonic) ----------------
__global__ void router_k(const float* __restrict__ x, const float* __restrict__ Wr,
                         const float* __restrict__ br) {
    int warp = threadIdx.x >> 5, lane = threadIdx.x & 31;
    int t = blockIdx.x * 8 + warp;
    const float* xp = x + (size_t)t * Dm + lane * 16;
    float4 xv[4];
#pragma unroll
    for (int i = 0; i < 4; i++) xv[i] = *(const float4*)(xp + i * 4);
    float lg[32];
#pragma unroll 1
    for (int n = 0; n < 32; n++) {
        const float* wp = Wr + n * Dm + lane * 16;
        float acc = 0.f;
#pragma unroll
        for (int i = 0; i < 4; i++) {
            float4 w = *(const float4*)(wp + i * 4);
            acc += xv[i].x * w.x + xv[i].y * w.y + xv[i].z * w.z + xv[i].w * w.w;
        }
#pragma unroll
        for (int o = 16; o; o >>= 1) acc += __shfl_xor_sync(0xffffffffu, acc, o);
        lg[n] = acc + br[n];
    }
    if (lane == 0) {
        unsigned used = 0;
        for (int k2 = 0; k2 < 4; k2++) {
            float best = -1e30f; int bi = 0;
            for (int n = 0; n < 32; n++)
                if (!((used >> n) & 1u) && lg[n] > best) { best = lg[n]; bi = n; }
            used |= 1u << bi;
            g_idx[t * 4 + k2] = bi;
        }
    }
}

__global__ void zero_k() { if (threadIdx.x < Np) g_cnt[threadIdx.x] = 0; }

__global__ void build_k() {
    int e = blockIdx.x * 256 + threadIdx.x;
    if (e >= T * Kk) return;
    int n = g_idx[e];
    int pos = atomicAdd(&g_cnt[n], 1);   // order irrelevant: each pair writes its own slot
    g_list[n * T + pos] = e;
}

// ---------------- 2. FFN pass 1: h = gelu(x @ W1[n] + b1[n]) ----------------
// grid (16 n-chunks, 32 m-tiles, 32 neurons), 128 thr. Tile 64x128, K=512, double-buffered.
__global__ __launch_bounds__(128, 3)
void ffn1_k(const float* __restrict__ x, const float* __restrict__ W1,
            const float* __restrict__ b1) {
    int n = blockIdx.z, tile = blockIdx.y, nb = blockIdx.x * 128;
    int cnt = g_cnt[n];
    int base = tile * 64;
    if (base >= cnt) return;
    __shared__ __align__(16) float asd[2 * KTILE_FLOATS];
    __shared__ __align__(16) float bsk[2 * KTILE_FLOATS];
    __shared__ int es[64];
    int tid = threadIdx.x;
    if (tid < 64) es[tid] = (base + tid < cnt) ? g_list[n * T + base + tid] : -1;
    __syncthreads();

    int tx = tid & 15, ty = tid >> 4, m0 = ty * 8, n0 = tx * 8;
    unsigned long long acc[32];
#pragma unroll
    for (int i = 0; i < 32; i++) acc[i] = 0ull;

    int arow = tid >> 1, kh = (tid & 1) * 8;
    int e_arow = es[arow];
    const float* aptr = (e_arow >= 0) ? (x + (size_t)(e_arow >> 2) * Dm + kh) : 0;
    int brow = tid >> 3, bcol = (tid & 7) * 16;
    const float* wbase = W1 + (size_t)n * Dm * Hd + nb + (size_t)brow * Hd + bcol;

    float4 a0 = make_float4(0.f, 0.f, 0.f, 0.f), a1 = a0;
    float4 w0, w1, w2, w3;
    if (aptr) { a0 = *(const float4*)(aptr); a1 = *(const float4*)(aptr + 4); }
    w0 = *(const float4*)(wbase);     w1 = *(const float4*)(wbase + 4);
    w2 = *(const float4*)(wbase + 8); w3 = *(const float4*)(wbase + 12);
    store_dupA_k(asd + kh * RPAD + 2 * arow, a0, a1);
    store_B_k(bsk + brow * RPAD + bcol, w0, w1, w2, w3);
    __syncthreads();

    const int NIT = Dm / 16;
#pragma unroll 1
    for (int it = 0; it < NIT; it++) {
        int buf = it & 1;
        if (it + 1 < NIT) {
            int k0 = (it + 1) * 16;
            if (aptr) { a0 = *(const float4*)(aptr + k0); a1 = *(const float4*)(aptr + k0 + 4); }
            const float* wp = wbase + (size_t)k0 * Hd;
            w0 = *(const float4*)(wp);     w1 = *(const float4*)(wp + 4);
            w2 = *(const float4*)(wp + 8); w3 = *(const float4*)(wp + 12);
        }
        mainloop16d(asd + buf * KTILE_FLOATS, bsk + buf * KTILE_FLOATS, m0, n0, acc);
        if (it + 1 < NIT) {
            int nb2 = (it + 1) & 1;
            store_dupA_k(asd + nb2 * KTILE_FLOATS + kh * RPAD + 2 * arow, a0, a1);
            store_B_k(bsk + nb2 * KTILE_FLOATS + brow * RPAD + bcol, w0, w1, w2, w3);
        }
        __syncthreads();
    }

    int col = nb + n0;
    float4 bb0 = *(const float4*)&b1[n * Hd + col];
    float4 bb1 = *(const float4*)&b1[n * Hd + col + 4];
#pragma unroll
    for (int r = 0; r < 8; r++) {
        int e = es[m0 + r];
        if (e < 0) continue;
        U2 p0, p1, p2, p3;
        p0.u = acc[r * 4 + 0]; p1.u = acc[r * 4 + 1];
        p2.u = acc[r * 4 + 2]; p3.u = acc[r * 4 + 3];
        float4 o0, o1;
        o0.x = gelu_f(p0.f.x + bb0.x); o0.y = gelu_f(p0.f.y + bb0.y);
        o0.z = gelu_f(p1.f.x + bb0.z); o0.w = gelu_f(p1.f.y + bb0.w);
        o1.x = gelu_f(p2.f.x + bb1.x); o1.y = gelu_f(p2.f.y + bb1.y);
        o1.z = gelu_f(p3.f.x + bb1.z); o1.w = gelu_f(p3.f.y + bb1.w);
        float* op = &g_h[(size_t)e * Hd + col];
        *(float4*)op = o0;
        *(float4*)(op + 4) = o1;
    }
}

// ---------------- 3. FFN pass 2: out_pair = h @ W2[n] + b2[n] ----------------
// grid (4 n-chunks, 32 m-tiles, 32 neurons), 128 thr. Tile 64x128, K=2048, double-buffered.
__global__ __launch_bounds__(128, 3)
void ffn2_k(const float* __restrict__ W2, const float* __restrict__ b2) {
    int n = blockIdx.z, tile = blockIdx.y, nb = blockIdx.x * 128;
    int cnt = g_cnt[n];
    int base = tile * 64;
    if (base >= cnt) return;
    __shared__ __align__(16) float asd[2 * KTILE_FLOATS];
    __shared__ __align__(16) float bsk[2 * KTILE_FLOATS];
    __shared__ int es[64];
    int tid = threadIdx.x;
    if (tid < 64) es[tid] = (base + tid < cnt) ? g_list[n * T + base + tid] : -1;
    __syncthreads();

    int tx = tid & 15, ty = tid >> 4, m0 = ty * 8, n0 = tx * 8;
    unsigned long long acc[32];
#pragma unroll
    for (int i = 0; i < 32; i++) acc[i] = 0ull;

    int arow = tid >> 1, kh = (tid & 1) * 8;
    int e_arow = es[arow];
    const float* aptr = (e_arow >= 0) ? (g_h + (size_t)e_arow * Hd + kh) : 0;
    int brow = tid >> 3, bcol = (tid & 7) * 16;
    const float* wbase = W2 + (size_t)n * Hd * Dm + nb + (size_t)brow * Dm + bcol;

    float4 a0 = make_float4(0.f, 0.f, 0.f, 0.f), a1 = a0;
    float4 w0, w1, w2, w3;
    if (aptr) { a0 = *(const float4*)(aptr); a1 = *(const float4*)(aptr + 4); }
    w0 = *(const float4*)(wbase);     w1 = *(const float4*)(wbase + 4);
    w2 = *(const float4*)(wbase + 8); w3 = *(const float4*)(wbase + 12);
    store_dupA_k(asd + kh * RPAD + 2 * arow, a0, a1);
    store_B_k(bsk + brow * RPAD + bcol, w0, w1, w2, w3);
    __syncthreads();

    const int NIT = Hd / 16;
#pragma unroll 1
    for (int it = 0; it < NIT; it++) {
        int buf = it & 1;
        if (it + 1 < NIT) {
            int k0 = (it + 1) * 16;
            if (aptr) { a0 = *(const float4*)(aptr + k0); a1 = *(const float4*)(aptr + k0 + 4); }
            const float* wp = wbase + (size_t)k0 * Dm;
            w0 = *(const float4*)(wp);     w1 = *(const float4*)(wp + 4);
            w2 = *(const float4*)(wp + 8); w3 = *(const float4*)(wp + 12);
        }
        mainloop16d(asd + buf * KTILE_FLOATS, bsk + buf * KTILE_FLOATS, m0, n0, acc);
        if (it + 1 < NIT) {
            int nb2 = (it + 1) & 1;
            store_dupA_k(asd + nb2 * KTILE_FLOATS + kh * RPAD + 2 * arow, a0, a1);
            store_B_k(bsk + nb2 * KTILE_FLOATS + brow * RPAD + bcol, w0, w1, w2, w3);
        }
        __syncthreads();
    }

    int col = nb + n0;
    float4 bb0 = *(const float4*)&b2[n * Dm + col];
    float4 bb1 = *(const float4*)&b2[n * Dm + col + 4];
#pragma unroll
    for (int r = 0; r < 8; r++) {
        int e = es[m0 + r];
        if (e < 0) continue;
        U2 p0, p1, p2, p3;
        p0.u = acc[r * 4 + 0]; p1.u = acc[r * 4 + 1];
        p2.u = acc[r * 4 + 2]; p3.u = acc[r * 4 + 3];
        float4 o0 = make_float4(p0.f.x + bb0.x, p0.f.y + bb0.y, p1.f.x + bb0.z, p1.f.y + bb0.w);
        float4 o1 = make_float4(p2.f.x + bb1.x, p2.f.y + bb1.y, p3.f.x + bb1.z, p3.f.y + bb1.w);
        float* op = &g_pairs[(size_t)e * Dm + col];
        *(float4*)op = o0;
        *(float4*)(op + 4) = o1;
    }
}

// ---------------- 4. mean over k ----------------
__global__ void reduce_k() {
    int id = blockIdx.x * 256 + threadIdx.x;
    if (id >= T * Dm / 4) return;
    int t = id >> 7, c4 = (id & 127) << 2;
    float4 s = make_float4(0.f, 0.f, 0.f, 0.f);
#pragma unroll
    for (int k2 = 0; k2 < 4; k2++) {
        float4 v = *(const float4*)&g_pairs[(size_t)(t * 4 + k2) * Dm + c4];
        s.x += v.x; s.y += v.y; s.z += v.z; s.w += v.w;
    }
    s.x *= 0.25f; s.y *= 0.25f; s.z *= 0.25f; s.w *= 0.25f;
    *(float4*)&g_nout[(size_t)t * Dm + c4] = s;
}

// ---------------- 5. weight transpose (W[R,C] -> WT[C,R]) ----------------
__global__ void transpose_k(const float* __restrict__ W, float* __restrict__ WT,
                            int R, int C) {
    __shared__ float tile[32][33];
    int r0 = blockIdx.y * 32, c0 = blockIdx.x * 32;
    int r = r0 + threadIdx.y, c = c0 + threadIdx.x;
#pragma unroll
    for (int i = 0; i < 32; i += 8)
        if (r + i < R && c < C) tile[threadIdx.y + i][threadIdx.x] = W[(size_t)(r + i) * C + c];
    __syncthreads();
    int rt = c0 + threadIdx.y, ct = r0 + threadIdx.x;
#pragma unroll
    for (int i = 0; i < 32; i += 8)
        if (rt + i < C && ct < R) WT[(size_t)(rt + i) * R + ct] = tile[threadIdx.x][threadIdx.y + i];
}

// ---------------- 6. dense GEMM: C[M,Nc] = A[M,512] @ WT[512,Nc] + bias ----------------
// grid (Nc/128, M/64), 128 thr. Tile 64x128, K=512, double-buffered.
__global__ __launch_bounds__(128, 3)
void gemm_k(const float* __restrict__ A, const float* __restrict__ WT,
            const float* __restrict__ bias, float* __restrict__ C, int Nc) {
    int nb = blockIdx.x * 128, mg = blockIdx.y * 64;
    __shared__ __align__(16) float asd[2 * KTILE_FLOATS];
    __shared__ __align__(16) float bsk[2 * KTILE_FLOATS];
    int tid = threadIdx.x;
    int tx = tid & 15, ty = tid >> 4, m0 = ty * 8, n0 = tx * 8;
    unsigned long long acc[32];
#pragma unroll
    for (int i = 0; i < 32; i++) acc[i] = 0ull;

    int arow = tid >> 1, kh = (tid & 1) * 8;
    const float* aptr = A + (size_t)(mg + arow) * Dm + kh;
    int brow = tid >> 3, bcol = (tid & 7) * 16;
    const float* wbase = WT + nb + (size_t)brow * Nc + bcol;

    float4 a0 = *(const float4*)(aptr), a1 = *(const float4*)(aptr + 4);
    float4 w0 = *(const float4*)(wbase),     w1 = *(const float4*)(wbase + 4);
    float4 w2 = *(const float4*)(wbase + 8), w3 = *(const float4*)(wbase + 12);
    store_dupA_k(asd + kh * RPAD + 2 * arow, a0, a1);
    store_B_k(bsk + brow * RPAD + bcol, w0, w1, w2, w3);
    __syncthreads();

    const int NIT = Dm / 16;
#pragma unroll 1
    for (int it = 0; it < NIT; it++) {
        int buf = it & 1;
        if (it + 1 < NIT) {
            int k0 = (it + 1) * 16;
            a0 = *(const float4*)(aptr + k0); a1 = *(const float4*)(aptr + k0 + 4);
            const float* wp = wbase + (size_t)k0 * Nc;
            w0 = *(const float4*)(wp);     w1 = *(const float4*)(wp + 4);
            w2 = *(const float4*)(wp + 8); w3 = *(const float4*)(wp + 12);
        }
        mainloop16d(asd + buf * KTILE_FLOATS, bsk + buf * KTILE_FLOATS, m0, n0, acc);
        if (it + 1 < NIT) {
            int nb2 = (it + 1) & 1;
            store_dupA_k(asd + nb2 * KTILE_FLOATS + kh * RPAD + 2 * arow, a0, a1);
            store_B_k(bsk + nb2 * KTILE_FLOATS + brow * RPAD + bcol, w0, w1, w2, w3);
        }
        __syncthreads();
    }

    int col = nb + n0;
    float4 bb0 = *(const float4*)&bias[col];
    float4 bb1 = *(const float4*)&bias[col + 4];
#pragma unroll
    for (int r = 0; r < 8; r++) {
        U2 p0, p1, p2, p3;
        p0.u = acc[r * 4 + 0]; p1.u = acc[r * 4 + 1];
        p2.u = acc[r * 4 + 2]; p3.u = acc[r * 4 + 3];
        float4 o0 = make_float4(p0.f.x + bb0.x, p0.f.y + bb0.y, p1.f.x + bb0.z, p1.f.y + bb0.w);
        float4 o1 = make_float4(p2.f.x + bb1.x, p2.f.y + bb1.y, p3.f.x + bb1.z, p3.f.y + bb1.w);
        float* op = &C[(size_t)(mg + m0 + r) * Nc + col];
        *(float4*)op = o0;
        *(float4*)(op + 4) = o1;
    }
}

// ---------------- 7. attention: flash-style, q-tile 64, kv-tile 64 ----------------
// grid (Sd/64, NHd, Bd), 256 thr (8 warps, each owns 8 q rows).
// dynamic smem: Qs[64][68] (d-major), KPs[64][68] (Ks d-major, then Ps q-major), Vs[64][68] (d-major)
__global__ __launch_bounds__(256)
void attn2_k() {
    extern __shared__ float sm[];
    float* Qs  = sm;
    float* KPs = sm + AT_REG;
    float* Vs  = sm + 2 * AT_REG;
    int q0 = blockIdx.x * 64, h = blockIdx.y, b = blockIdx.z;
    int tid = threadIdx.x, lane = tid & 31, w = tid >> 5;
    int qr = w * 8;

    // load Q transposed (Qs[d][q]) with 1/sqrt(64) folded in
    {
        int r = tid >> 2, c0 = (tid & 3) * 16;
        const float* qp = g_qkv + (size_t)(b * Sd + q0 + r) * D3 + h * HDd + c0;
#pragma unroll
        for (int i = 0; i < 4; i++) {
            float4 v = *(const float4*)(qp + i * 4);
            Qs[(c0 + i * 4 + 0) * AT_PAD + r] = v.x * 0.125f;
            Qs[(c0 + i * 4 + 1) * AT_PAD + r] = v.y * 0.125f;
            Qs[(c0 + i * 4 + 2) * AT_PAD + r] = v.z * 0.125f;
            Qs[(c0 + i * 4 + 3) * AT_PAD + r] = v.w * 0.125f;
        }
    }

    float m[8], l[8], o0[8], o1[8];
#pragma unroll
    for (int r = 0; r < 8; r++) { m[r] = -1e30f; l[r] = 0.f; o0[r] = 0.f; o1[r] = 0.f; }

#pragma unroll 1
    for (int j0 = 0; j0 < Sd; j0 += 64) {
        __syncthreads();   // prev AV done; (first iter: nothing)
        // load K (transposed -> KPs[d][k]) and V (transposed -> Vs[d][k])
        {
            int r = tid >> 2, c0 = (tid & 3) * 16;
            const float* kp = g_qkv + (size_t)(b * Sd + j0 + r) * D3 + Dm + h * HDd + c0;
            const float* vp = kp + Dm;
#pragma unroll
            for (int i = 0; i < 4; i++) {
                float4 kv = *(const float4*)(kp + i * 4);
                KPs[(c0 + i * 4 + 0) * AT_PAD + r] = kv.x;
                KPs[(c0 + i * 4 + 1) * AT_PAD + r] = kv.y;
                KPs[(c0 + i * 4 + 2) * AT_PAD + r] = kv.z;
                KPs[(c0 + i * 4 + 3) * AT_PAD + r] = kv.w;
                float4 vv = *(const float4*)(vp + i * 4);
                Vs[(c0 + i * 4 + 0) * AT_PAD + r] = vv.x;
                Vs[(c0 + i * 4 + 1) * AT_PAD + r] = vv.y;
                Vs[(c0 + i * 4 + 2) * AT_PAD + r] = vv.z;
                Vs[(c0 + i * 4 + 3) * AT_PAD + r] = vv.w;
            }
        }
        __syncthreads();   // K/V visible, Q visible (first iter)

        // S = Q K^T : lane owns keys {2*lane, 2*lane+1}, warp owns 8 q rows
        float s[8][2];
#pragma unroll
        for (int r = 0; r < 8; r++) { s[r][0] = 0.f; s[r][1] = 0.f; }
#pragma unroll 8
        for (int d = 0; d < 64; d++) {
            float4 qa = *(const float4*)&Qs[d * AT_PAD + qr];
            float4 qb = *(const float4*)&Qs[d * AT_PAD + qr + 4];
            float2 kk = *(const float2*)&KPs[d * AT_PAD + 2 * lane];
            s[0][0] += qa.x * kk.x; s[0][1] += qa.x * kk.y;
            s[1][0] += qa.y * kk.x; s[1][1] += qa.y * kk.y;
            s[2][0] += qa.z * kk.x; s[2][1] += qa.z * kk.y;
            s[3][0] += qa.w * kk.x; s[3][1] += qa.w * kk.y;
            s[4][0] += qb.x * kk.x; s[4][1] += qb.x * kk.y;
            s[5][0] += qb.y * kk.x; s[5][1] += qb.y * kk.y;
            s[6][0] += qb.z * kk.x; s[6][1] += qb.z * kk.y;
            s[7][0] += qb.w * kk.x; s[7][1] += qb.w * kk.y;
        }

        // streaming softmax update
#pragma unroll
        for (int r = 0; r < 8; r++) {
            float tmax = fmaxf(s[r][0], s[r][1]);
#pragma unroll
            for (int o = 16; o; o >>= 1) tmax = fmaxf(tmax, __shfl_xor_sync(0xffffffffu, tmax, o));
            float mn = fmaxf(m[r], tmax);
            float corr = __expf(m[r] - mn);
            float p0 = __expf(s[r][0] - mn);
            float p1 = __expf(s[r][1] - mn);
            float rs = p0 + p1;
#pragma unroll
            for (int o = 16; o; o >>= 1) rs += __shfl_xor_sync(0xffffffffu, rs, o);
            l[r] = l[r] * corr + rs;
            m[r] = mn;
            o0[r] *= corr; o1[r] *= corr;
            s[r][0] = p0; s[r][1] = p1;
        }
        __syncthreads();   // all warps done reading KPs as Ks

        // write P (q-major): KPs[q][k]
#pragma unroll
        for (int r = 0; r < 8; r++)
            *(float2*)&KPs[(qr + r) * AT_PAD + 2 * lane] = make_float2(s[r][0], s[r][1]);
        __syncthreads();

        // O += P V : lane owns d = lane and lane+32
        const float* vr0 = &Vs[lane * AT_PAD];
        const float* vr1 = &Vs[(lane + 32) * AT_PAD];
#pragma unroll 4
        for (int k4 = 0; k4 < 16; k4++) {
            float4 v0 = *(const float4*)(vr0 + 4 * k4);
            float4 v1 = *(const float4*)(vr1 + 4 * k4);
#pragma unroll
            for (int r = 0; r < 8; r++) {
                float4 p = *(const float4*)&KPs[(qr + r) * AT_PAD + 4 * k4];
                o0[r] += p.x * v0.x + p.y * v0.y + p.z * v0.z + p.w * v0.w;
                o1[r] += p.x * v1.x + p.y * v1.y + p.z * v1.z + p.w * v1.w;
            }
        }
    }

    // epilogue: normalize + store
#pragma unroll
    for (int r = 0; r < 8; r++) {
        float inv = 1.0f / l[r];
        int t = b * Sd + q0 + qr + r;
        g_attno[(size_t)t * Dm + h * HDd + lane] = o0[r] * inv;
        g_attno[(size_t)t * Dm + h * HDd + lane + 32] = o1[r] * inv;
    }
}

// ---------------- 8. fused residual + LN1 + residual + LN2 ----------------
__global__ void ln_k(const float* __restrict__ x,
                     const float* __restrict__ ln1w, const float* __restrict__ ln1b,
                     const float* __restrict__ ln2w, const float* __restrict__ ln2b,
                     float* __restrict__ out) {
    int t = blockIdx.x, tid = threadIdx.x;  // 256 threads, 2 elems each
    __shared__ float r1[8], r2[8];
    __shared__ float mu_s, rs_s;
    size_t off = (size_t)t * Dm;
    float a0 = x[off + tid] + g_attnout[off + tid];
    float a1 = x[off + 256 + tid] + g_attnout[off + 256 + tid];
    float s = a0 + a1, ss = a0 * a0 + a1 * a1;
#pragma unroll
    for (int o = 16; o; o >>= 1) {
        s += __shfl_xor_sync(0xffffffffu, s, o);
        ss += __shfl_xor_sync(0xffffffffu, ss, o);
    }
    if ((tid & 31) == 0) { r1[tid >> 5] = s; r2[tid >> 5] = ss; }
    __syncthreads();
    if (tid == 0) {
        float S = 0.f, SS = 0.f;
#pragma unroll
        for (int i = 0; i < 8; i++) { S += r1[i]; SS += r2[i]; }
        float mu = S * (1.0f / 512.0f);
        mu_s = mu;
        rs_s = rsqrtf(SS * (1.0f / 512.0f) - mu * mu + 1e-5f);
    }
    __syncthreads();
    float mu = mu_s, rs = rs_s;
    float z0 = (a0 - mu) * rs * ln1w[tid] + ln1b[tid] + g_nout[off + tid];
    float z1 = (a1 - mu) * rs * ln1w[256 + tid] + ln1b[256 + tid] + g_nout[off + 256 + tid];
    s = z0 + z1; ss = z0 * z0 + z1 * z1;
#pragma unroll
    for (int o = 16; o; o >>= 1) {
        s += __shfl_xor_sync(0xffffffffu, s, o);
        ss += __shfl_xor_sync(0xffffffffu, ss, o);
    }
    __syncthreads();
    if ((tid & 31) == 0) { r1[tid >> 5] = s; r2[tid >> 5] = ss; }
    __syncthreads();
    if (tid == 0) {
        float S = 0.f, SS = 0.f;
#pragma unroll
        for (int i = 0; i < 8; i++) { S += r1[i]; SS += r2[i]; }
        float mu2 = S * (1.0f / 512.0f);
        mu_s = mu2;
        rs_s = rsqrtf(SS * (1.0f / 512.0f) - mu2 * mu2 + 1e-5f);
    }
    __syncthreads();
    mu = mu_s; rs = rs_s;
    out[off + tid] = (z0 - mu) * rs * ln2w[tid] + ln2b[tid];
    out[off + 256 + tid] = (z1 - mu) * rs * ln2w[256 + tid] + ln2b[256 + tid];
}

// ---------------- launcher ----------------
extern "C" void kernel_launch(void* const* d_in, const int* in_sizes, int n_in,
                              void* d_out, int out_size) {
    const float* x    = (const float*)d_in[0];
    const float* Wr   = (const float*)d_in[1];
    const float* br   = (const float*)d_in[2];
    const float* W1   = (const float*)d_in[3];
    const float* b1   = (const float*)d_in[4];
    const float* W2   = (const float*)d_in[5];
    const float* b2   = (const float*)d_in[6];
    const float* Wqkv = (const float*)d_in[7];
    const float* bqkv = (const float*)d_in[8];
    const float* Wo   = (const float*)d_in[9];
    const float* bo   = (const float*)d_in[10];
    const float* ln1w = (const float*)d_in[11];
    const float* ln1b = (const float*)d_in[12];
    const float* ln2w = (const float*)d_in[13];
    const float* ln2b = (const float*)d_in[14];
    float* out = (float*)d_out;

    float *p_nout, *p_qkv, *p_attno, *p_attnout, *p_wqkvt, *p_wot;
    cudaGetSymbolAddress((void**)&p_nout, g_nout);
    cudaGetSymbolAddress((void**)&p_qkv, g_qkv);
    cudaGetSymbolAddress((void**)&p_attno, g_attno);
    cudaGetSymbolAddress((void**)&p_attnout, g_attnout);
    cudaGetSymbolAddress((void**)&p_wqkvt, g_WqkvT);
    cudaGetSymbolAddress((void**)&p_wot, g_WoT);

    static int attn_attr_set = 0;
    if (!attn_attr_set) {
        cudaFuncSetAttribute(attn2_k, cudaFuncAttributeMaxDynamicSharedMemorySize, SMEM_ATTN);
        attn_attr_set = 1;
    }

    // router + list build
    router_k<<<T / 8, 256>>>(x, Wr, br);
    zero_k<<<1, 32>>>();
    build_k<<<(T * Kk + 255) / 256, 256>>>();

    // sparse FFN (only selected neuron-token pairs), pipelined FFMA2 GEMMs
    ffn1_k<<<dim3(16, 32, 32), 128>>>(x, W1, b1);
    ffn2_k<<<dim3(4, 32, 32), 128>>>(W2, b2);
    reduce_k<<<(T * Dm / 4 + 255) / 256, 256>>>();

    // attention
    transpose_k<<<dim3(16, 48), dim3(32, 8)>>>(Wqkv, p_wqkvt, D3, Dm);
    transpose_k<<<dim3(16, 16), dim3(32, 8)>>>(Wo, p_wot, Dm, Dm);
    gemm_k<<<dim3(D3 / 128, T / 64), 128>>>(p_nout, p_wqkvt, bqkv, p_qkv, D3);
    attn2_k<<<dim3(Sd / 64, NHd, Bd), 256, SMEM_ATTN>>>();
    gemm_k<<<dim3(Dm / 128, T / 64), 128>>>(p_attno, p_wot, bo, p_attnout, Dm);

    // epilogue
    ln_k<<<T, 256>>>(x, ln1w, ln1b, ln2w, ln2b, out);
}

// round 4
// speedup vs baseline: 2.2534x; 1.0043x over previous
#include <cuda_runtime.h>
#include <math.h>

// Problem constants
#define T   2048      // B*S tokens
#define Dm  512
#define Np  32
#define Hd  2048
#define Kk  4
#define NHd 8
#define HDd 64
#define Sd  1024
#define Bd  2
#define D3  1536      // 3*Dm

#define RPAD 132            // k-major smem row length (floats): 128 data + 4 pad
#define KTILE_FLOATS (16 * RPAD)

// attention smem layout (dynamic): Qs[64][68], KPs[64][68], Vs[64][68]
#define AT_PAD 68
#define AT_REG (64 * AT_PAD)
#define SMEM_ATTN (3 * AT_REG * 4)

// ---------------- scratch (static device memory; no allocations) ----------------
__device__ int   g_idx[T * Kk];
__device__ int   g_cnt[Np];
__device__ int   g_list[Np * T];
__device__ float g_h[T * Kk * Hd];          // 64 MB  gelu(x@W1) per selected pair
__device__ float g_pairs[T * Kk * Dm];      // 16 MB  per-pair FFN outputs
__device__ float g_nout[T * Dm];            // neuron_out (mean over k)
__device__ float g_qkv[T * D3];
__device__ float g_attno[T * Dm];           // attention head outputs (pre out-proj)
__device__ float g_attnout[T * Dm];         // after out-proj
__device__ float g_WqkvT[Dm * D3];          // [512,1536]
__device__ float g_WoT[Dm * Dm];            // [512,512]

__device__ __forceinline__ float gelu_f(float v) {
    float u = 0.7978845608028654f * (v + 0.044715f * v * v * v);
    return 0.5f * v * (1.0f + tanhf(u));
}

__device__ __forceinline__ unsigned long long ffma2(unsigned long long a,
                                                    unsigned long long b,
                                                    unsigned long long c) {
    unsigned long long d;
    asm("fma.rn.f32x2 %0, %1, %2, %3;" : "=l"(d) : "l"(a), "l"(b), "l"(c));
    return d;
}

union U2 { unsigned long long u; float2 f; };

// Inner product over a 16-k smem tile, k-major layout.
// asd: duplicated A [k][2*m] (rows RPAD floats). bsk: B [k][n] (rows RPAD floats).
__device__ __forceinline__ void mainloop16d(const float* __restrict__ asd,
                                            const float* __restrict__ bsk,
                                            int m0, int n0,
                                            unsigned long long acc[32]) {
#pragma unroll
    for (int k = 0; k < 16; k++) {
        const ulonglong2* apq = (const ulonglong2*)(asd + k * RPAD + 2 * m0);
        ulonglong2 aP0 = apq[0], aP1 = apq[1], aP2 = apq[2], aP3 = apq[3];
        const ulonglong2* bp = (const ulonglong2*)(bsk + k * RPAD + n0);
        ulonglong2 bA = bp[0], bB = bp[1];
        unsigned long long a[8] = {aP0.x, aP0.y, aP1.x, aP1.y,
                                   aP2.x, aP2.y, aP3.x, aP3.y};
#pragma unroll
        for (int r = 0; r < 8; r++) {
            acc[r * 4 + 0] = ffma2(a[r], bA.x, acc[r * 4 + 0]);
            acc[r * 4 + 1] = ffma2(a[r], bA.y, acc[r * 4 + 1]);
            acc[r * 4 + 2] = ffma2(a[r], bB.x, acc[r * 4 + 2]);
            acc[r * 4 + 3] = ffma2(a[r], bB.y, acc[r * 4 + 3]);
        }
    }
}

// store 8 duplicated A values into k-major tile: ad + i*RPAD <- {v,v}
__device__ __forceinline__ void store_dupA_k(float* ad, float4 a0, float4 a1) {
    *(float2*)(ad + 0 * RPAD) = make_float2(a0.x, a0.x);
    *(float2*)(ad + 1 * RPAD) = make_float2(a0.y, a0.y);
    *(float2*)(ad + 2 * RPAD) = make_float2(a0.z, a0.z);
    *(float2*)(ad + 3 * RPAD) = make_float2(a0.w, a0.w);
    *(float2*)(ad + 4 * RPAD) = make_float2(a1.x, a1.x);
    *(float2*)(ad + 5 * RPAD) = make_float2(a1.y, a1.y);
    *(float2*)(ad + 6 * RPAD) = make_float2(a1.z, a1.z);
    *(float2*)(ad + 7 * RPAD) = make_float2(a1.w, a1.w);
}

__device__ __forceinline__ void store_B_k(float* bd, float4 w0, float4 w1,
                                          float4 w2, float4 w3) {
    *(float4*)(bd + 0) = w0; *(float4*)(bd + 4) = w1;
    *(float4*)(bd + 8) = w2; *(float4*)(bd + 12) = w3;
}

// ---------------- 1. router: top-4 of logits (softmax is monotonic) ----------------
__global__ void router_k(const float* __restrict__ x, const float* __restrict__ Wr,
                         const float* __restrict__ br) {
    int warp = threadIdx.x >> 5, lane = threadIdx.x & 31;
    int t = blockIdx.x * 8 + warp;
    const float* xp = x + (size_t)t * Dm + lane * 16;
    float4 xv[4];
#pragma unroll
    for (int i = 0; i < 4; i++) xv[i] = *(const float4*)(xp + i * 4);
    float lg[32];
#pragma unroll 1
    for (int n = 0; n < 32; n++) {
        const float* wp = Wr + n * Dm + lane * 16;
        float acc = 0.f;
#pragma unroll
        for (int i = 0; i < 4; i++) {
            float4 w = *(const float4*)(wp + i * 4);
            acc += xv[i].x * w.x + xv[i].y * w.y + xv[i].z * w.z + xv[i].w * w.w;
        }
#pragma unroll
        for (int o = 16; o; o >>= 1) acc += __shfl_xor_sync(0xffffffffu, acc, o);
        lg[n] = acc + br[n];
    }
    if (lane == 0) {
        unsigned used = 0;
        for (int k2 = 0; k2 < 4; k2++) {
            float best = -1e30f; int bi = 0;
            for (int n = 0; n < 32; n++)
                if (!((used >> n) & 1u) && lg[n] > best) { best = lg[n]; bi = n; }
            used |= 1u << bi;
            g_idx[t * 4 + k2] = bi;
        }
    }
}

__global__ void zero_k() { if (threadIdx.x < Np) g_cnt[threadIdx.x] = 0; }

__global__ void build_k() {
    int e = blockIdx.x * 256 + threadIdx.x;
    if (e >= T * Kk) return;
    int n = g_idx[e];
    int pos = atomicAdd(&g_cnt[n], 1);   // order irrelevant: each pair writes its own slot
    g_list[n * T + pos] = e;
}

// ---------------- 2. FFN pass 1: h = gelu(x @ W1[n] + b1[n]) ----------------
// grid (16 n-chunks, 32 m-tiles, 32 neurons), 128 thr. Tile 64x128, K=512, double-buffered.
__global__ __launch_bounds__(128, 3)
void ffn1_k(const float* __restrict__ x, const float* __restrict__ W1,
            const float* __restrict__ b1) {
    int n = blockIdx.z, tile = blockIdx.y, nb = blockIdx.x * 128;
    int cnt = g_cnt[n];
    int base = tile * 64;
    if (base >= cnt) return;
    __shared__ __align__(16) float asd[2 * KTILE_FLOATS];
    __shared__ __align__(16) float bsk[2 * KTILE_FLOATS];
    __shared__ int es[64];
    int tid = threadIdx.x;
    if (tid < 64) es[tid] = (base + tid < cnt) ? g_list[n * T + base + tid] : -1;
    __syncthreads();

    int tx = tid & 15, ty = tid >> 4, m0 = ty * 8, n0 = tx * 8;
    unsigned long long acc[32];
#pragma unroll
    for (int i = 0; i < 32; i++) acc[i] = 0ull;

    int arow = tid >> 1, kh = (tid & 1) * 8;
    int e_arow = es[arow];
    const float* aptr = (e_arow >= 0) ? (x + (size_t)(e_arow >> 2) * Dm + kh) : 0;
    int brow = tid >> 3, bcol = (tid & 7) * 16;
    const float* wbase = W1 + (size_t)n * Dm * Hd + nb + (size_t)brow * Hd + bcol;

    float4 a0 = make_float4(0.f, 0.f, 0.f, 0.f), a1 = a0;
    float4 w0, w1, w2, w3;
    if (aptr) { a0 = *(const float4*)(aptr); a1 = *(const float4*)(aptr + 4); }
    w0 = *(const float4*)(wbase);     w1 = *(const float4*)(wbase + 4);
    w2 = *(const float4*)(wbase + 8); w3 = *(const float4*)(wbase + 12);
    store_dupA_k(asd + kh * RPAD + 2 * arow, a0, a1);
    store_B_k(bsk + brow * RPAD + bcol, w0, w1, w2, w3);
    __syncthreads();

    const int NIT = Dm / 16;
#pragma unroll 1
    for (int it = 0; it < NIT; it++) {
        int buf = it & 1;
        if (it + 1 < NIT) {
            int k0 = (it + 1) * 16;
            if (aptr) { a0 = *(const float4*)(aptr + k0); a1 = *(const float4*)(aptr + k0 + 4); }
            const float* wp = wbase + (size_t)k0 * Hd;
            w0 = *(const float4*)(wp);     w1 = *(const float4*)(wp + 4);
            w2 = *(const float4*)(wp + 8); w3 = *(const float4*)(wp + 12);
        }
        mainloop16d(asd + buf * KTILE_FLOATS, bsk + buf * KTILE_FLOATS, m0, n0, acc);
        if (it + 1 < NIT) {
            int nb2 = (it + 1) & 1;
            store_dupA_k(asd + nb2 * KTILE_FLOATS + kh * RPAD + 2 * arow, a0, a1);
            store_B_k(bsk + nb2 * KTILE_FLOATS + brow * RPAD + bcol, w0, w1, w2, w3);
        }
        __syncthreads();
    }

    int col = nb + n0;
    float4 bb0 = *(const float4*)&b1[n * Hd + col];
    float4 bb1 = *(const float4*)&b1[n * Hd + col + 4];
#pragma unroll
    for (int r = 0; r < 8; r++) {
        int e = es[m0 + r];
        if (e < 0) continue;
        U2 p0, p1, p2, p3;
        p0.u = acc[r * 4 + 0]; p1.u = acc[r * 4 + 1];
        p2.u = acc[r * 4 + 2]; p3.u = acc[r * 4 + 3];
        float4 o0, o1;
        o0.x = gelu_f(p0.f.x + bb0.x); o0.y = gelu_f(p0.f.y + bb0.y);
        o0.z = gelu_f(p1.f.x + bb0.z); o0.w = gelu_f(p1.f.y + bb0.w);
        o1.x = gelu_f(p2.f.x + bb1.x); o1.y = gelu_f(p2.f.y + bb1.y);
        o1.z = gelu_f(p3.f.x + bb1.z); o1.w = gelu_f(p3.f.y + bb1.w);
        float* op = &g_h[(size_t)e * Hd + col];
        *(float4*)op = o0;
        *(float4*)(op + 4) = o1;
    }
}

// ---------------- 3. FFN pass 2: out_pair = h @ W2[n] + b2[n] ----------------
// grid (4 n-chunks, 32 m-tiles, 32 neurons), 128 thr. Tile 64x128, K=2048, double-buffered.
__global__ __launch_bounds__(128, 3)
void ffn2_k(const float* __restrict__ W2, const float* __restrict__ b2) {
    int n = blockIdx.z, tile = blockIdx.y, nb = blockIdx.x * 128;
    int cnt = g_cnt[n];
    int base = tile * 64;
    if (base >= cnt) return;
    __shared__ __align__(16) float asd[2 * KTILE_FLOATS];
    __shared__ __align__(16) float bsk[2 * KTILE_FLOATS];
    __shared__ int es[64];
    int tid = threadIdx.x;
    if (tid < 64) es[tid] = (base + tid < cnt) ? g_list[n * T + base + tid] : -1;
    __syncthreads();

    int tx = tid & 15, ty = tid >> 4, m0 = ty * 8, n0 = tx * 8;
    unsigned long long acc[32];
#pragma unroll
    for (int i = 0; i < 32; i++) acc[i] = 0ull;

    int arow = tid >> 1, kh = (tid & 1) * 8;
    int e_arow = es[arow];
    const float* aptr = (e_arow >= 0) ? (g_h + (size_t)e_arow * Hd + kh) : 0;
    int brow = tid >> 3, bcol = (tid & 7) * 16;
    const float* wbase = W2 + (size_t)n * Hd * Dm + nb + (size_t)brow * Dm + bcol;

    float4 a0 = make_float4(0.f, 0.f, 0.f, 0.f), a1 = a0;
    float4 w0, w1, w2, w3;
    if (aptr) { a0 = *(const float4*)(aptr); a1 = *(const float4*)(aptr + 4); }
    w0 = *(const float4*)(wbase);     w1 = *(const float4*)(wbase + 4);
    w2 = *(const float4*)(wbase + 8); w3 = *(const float4*)(wbase + 12);
    store_dupA_k(asd + kh * RPAD + 2 * arow, a0, a1);
    store_B_k(bsk + brow * RPAD + bcol, w0, w1, w2, w3);
    __syncthreads();

    const int NIT = Hd / 16;
#pragma unroll 1
    for (int it = 0; it < NIT; it++) {
        int buf = it & 1;
        if (it + 1 < NIT) {
            int k0 = (it + 1) * 16;
            if (aptr) { a0 = *(const float4*)(aptr + k0); a1 = *(const float4*)(aptr + k0 + 4); }
            const float* wp = wbase + (size_t)k0 * Dm;
            w0 = *(const float4*)(wp);     w1 = *(const float4*)(wp + 4);
            w2 = *(const float4*)(wp + 8); w3 = *(const float4*)(wp + 12);
        }
        mainloop16d(asd + buf * KTILE_FLOATS, bsk + buf * KTILE_FLOATS, m0, n0, acc);
        if (it + 1 < NIT) {
            int nb2 = (it + 1) & 1;
            store_dupA_k(asd + nb2 * KTILE_FLOATS + kh * RPAD + 2 * arow, a0, a1);
            store_B_k(bsk + nb2 * KTILE_FLOATS + brow * RPAD + bcol, w0, w1, w2, w3);
        }
        __syncthreads();
    }

    int col = nb + n0;
    float4 bb0 = *(const float4*)&b2[n * Dm + col];
    float4 bb1 = *(const float4*)&b2[n * Dm + col + 4];
#pragma unroll
    for (int r = 0; r < 8; r++) {
        int e = es[m0 + r];
        if (e < 0) continue;
        U2 p0, p1, p2, p3;
        p0.u = acc[r * 4 + 0]; p1.u = acc[r * 4 + 1];
        p2.u = acc[r * 4 + 2]; p3.u = acc[r * 4 + 3];
        float4 o0 = make_float4(p0.f.x + bb0.x, p0.f.y + bb0.y, p1.f.x + bb0.z, p1.f.y + bb0.w);
        float4 o1 = make_float4(p2.f.x + bb1.x, p2.f.y + bb1.y, p3.f.x + bb1.z, p3.f.y + bb1.w);
        float* op = &g_pairs[(size_t)e * Dm + col];
        *(float4*)op = o0;
        *(float4*)(op + 4) = o1;
    }
}

// ---------------- 4. mean over k ----------------
__global__ void reduce_k() {
    int id = blockIdx.x * 256 + threadIdx.x;
    if (id >= T * Dm / 4) return;
    int t = id >> 7, c4 = (id & 127) << 2;
    float4 s = make_float4(0.f, 0.f, 0.f, 0.f);
#pragma unroll
    for (int k2 = 0; k2 < 4; k2++) {
        float4 v = *(const float4*)&g_pairs[(size_t)(t * 4 + k2) * Dm + c4];
        s.x += v.x; s.y += v.y; s.z += v.z; s.w += v.w;
    }
    s.x *= 0.25f; s.y *= 0.25f; s.z *= 0.25f; s.w *= 0.25f;
    *(float4*)&g_nout[(size_t)t * Dm + c4] = s;
}

// ---------------- 5. weight transpose (W[R,C] -> WT[C,R]) ----------------
__global__ void transpose_k(const float* __restrict__ W, float* __restrict__ WT,
                            int R, int C) {
    __shared__ float tile[32][33];
    int r0 = blockIdx.y * 32, c0 = blockIdx.x * 32;
    int r = r0 + threadIdx.y, c = c0 + threadIdx.x;
#pragma unroll
    for (int i = 0; i < 32; i += 8)
        if (r + i < R && c < C) tile[threadIdx.y + i][threadIdx.x] = W[(size_t)(r + i) * C + c];
    __syncthreads();
    int rt = c0 + threadIdx.y, ct = r0 + threadIdx.x;
#pragma unroll
    for (int i = 0; i < 32; i += 8)
        if (rt + i < C && ct < R) WT[(size_t)(rt + i) * R + ct] = tile[threadIdx.x][threadIdx.y + i];
}

// ---------------- 6. dense GEMM: C[M,Nc] = A[M,512] @ WT[512,Nc] + bias ----------------
// grid (Nc/128, M/64), 128 thr. Tile 64x128, K=512, double-buffered.
__global__ __launch_bounds__(128, 3)
void gemm_k(const float* __restrict__ A, const float* __restrict__ WT,
            const float* __restrict__ bias, float* __restrict__ C, int Nc) {
    int nb = blockIdx.x * 128, mg = blockIdx.y * 64;
    __shared__ __align__(16) float asd[2 * KTILE_FLOATS];
    __shared__ __align__(16) float bsk[2 * KTILE_FLOATS];
    int tid = threadIdx.x;
    int tx = tid & 15, ty = tid >> 4, m0 = ty * 8, n0 = tx * 8;
    unsigned long long acc[32];
#pragma unroll
    for (int i = 0; i < 32; i++) acc[i] = 0ull;

    int arow = tid >> 1, kh = (tid & 1) * 8;
    const float* aptr = A + (size_t)(mg + arow) * Dm + kh;
    int brow = tid >> 3, bcol = (tid & 7) * 16;
    const float* wbase = WT + nb + (size_t)brow * Nc + bcol;

    float4 a0 = *(const float4*)(aptr), a1 = *(const float4*)(aptr + 4);
    float4 w0 = *(const float4*)(wbase),     w1 = *(const float4*)(wbase + 4);
    float4 w2 = *(const float4*)(wbase + 8), w3 = *(const float4*)(wbase + 12);
    store_dupA_k(asd + kh * RPAD + 2 * arow, a0, a1);
    store_B_k(bsk + brow * RPAD + bcol, w0, w1, w2, w3);
    __syncthreads();

    const int NIT = Dm / 16;
#pragma unroll 1
    for (int it = 0; it < NIT; it++) {
        int buf = it & 1;
        if (it + 1 < NIT) {
            int k0 = (it + 1) * 16;
            a0 = *(const float4*)(aptr + k0); a1 = *(const float4*)(aptr + k0 + 4);
            const float* wp = wbase + (size_t)k0 * Nc;
            w0 = *(const float4*)(wp);     w1 = *(const float4*)(wp + 4);
            w2 = *(const float4*)(wp + 8); w3 = *(const float4*)(wp + 12);
        }
        mainloop16d(asd + buf * KTILE_FLOATS, bsk + buf * KTILE_FLOATS, m0, n0, acc);
        if (it + 1 < NIT) {
            int nb2 = (it + 1) & 1;
            store_dupA_k(asd + nb2 * KTILE_FLOATS + kh * RPAD + 2 * arow, a0, a1);
            store_B_k(bsk + nb2 * KTILE_FLOATS + brow * RPAD + bcol, w0, w1, w2, w3);
        }
        __syncthreads();
    }

    int col = nb + n0;
    float4 bb0 = *(const float4*)&bias[col];
    float4 bb1 = *(const float4*)&bias[col + 4];
#pragma unroll
    for (int r = 0; r < 8; r++) {
        U2 p0, p1, p2, p3;
        p0.u = acc[r * 4 + 0]; p1.u = acc[r * 4 + 1];
        p2.u = acc[r * 4 + 2]; p3.u = acc[r * 4 + 3];
        float4 o0 = make_float4(p0.f.x + bb0.x, p0.f.y + bb0.y, p1.f.x + bb0.z, p1.f.y + bb0.w);
        float4 o1 = make_float4(p2.f.x + bb1.x, p2.f.y + bb1.y, p3.f.x + bb1.z, p3.f.y + bb1.w);
        float* op = &C[(size_t)(mg + m0 + r) * Nc + col];
        *(float4*)op = o0;
        *(float4*)(op + 4) = o1;
    }
}

// ---------------- 7. attention: flash-style, q-tile 64, kv-tile 64 ----------------
// grid (Sd/64, NHd, Bd), 256 thr (8 warps, each owns 8 q rows).
// dynamic smem: Qs[64][68] (d-major), KPs[64][68] (Ks d-major, then Ps q-major), Vs[64][68] (d-major)
__global__ __launch_bounds__(256)
void attn2_k() {
    extern __shared__ float sm[];
    float* Qs  = sm;
    float* KPs = sm + AT_REG;
    float* Vs  = sm + 2 * AT_REG;
    int q0 = blockIdx.x * 64, h = blockIdx.y, b = blockIdx.z;
    int tid = threadIdx.x, lane = tid & 31, w = tid >> 5;
    int qr = w * 8;

    // load Q transposed (Qs[d][q]) with 1/sqrt(64) folded in
    {
        int r = tid >> 2, c0 = (tid & 3) * 16;
        const float* qp = g_qkv + (size_t)(b * Sd + q0 + r) * D3 + h * HDd + c0;
#pragma unroll
        for (int i = 0; i < 4; i++) {
            float4 v = *(const float4*)(qp + i * 4);
            Qs[(c0 + i * 4 + 0) * AT_PAD + r] = v.x * 0.125f;
            Qs[(c0 + i * 4 + 1) * AT_PAD + r] = v.y * 0.125f;
            Qs[(c0 + i * 4 + 2) * AT_PAD + r] = v.z * 0.125f;
            Qs[(c0 + i * 4 + 3) * AT_PAD + r] = v.w * 0.125f;
        }
    }

    float m[8], l[8], o0[8], o1[8];
#pragma unroll
    for (int r = 0; r < 8; r++) { m[r] = -1e30f; l[r] = 0.f; o0[r] = 0.f; o1[r] = 0.f; }

#pragma unroll 1
    for (int j0 = 0; j0 < Sd; j0 += 64) {
        __syncthreads();   // prev AV done; (first iter: nothing)
        // load K (transposed -> KPs[d][k]) and V (transposed -> Vs[d][k])
        {
            int r = tid >> 2, c0 = (tid & 3) * 16;
            const float* kp = g_qkv + (size_t)(b * Sd + j0 + r) * D3 + Dm + h * HDd + c0;
            const float* vp = kp + Dm;
#pragma unroll
            for (int i = 0; i < 4; i++) {
                float4 kv = *(const float4*)(kp + i * 4);
                KPs[(c0 + i * 4 + 0) * AT_PAD + r] = kv.x;
                KPs[(c0 + i * 4 + 1) * AT_PAD + r] = kv.y;
                KPs[(c0 + i * 4 + 2) * AT_PAD + r] = kv.z;
                KPs[(c0 + i * 4 + 3) * AT_PAD + r] = kv.w;
                float4 vv = *(const float4*)(vp + i * 4);
                Vs[(c0 + i * 4 + 0) * AT_PAD + r] = vv.x;
                Vs[(c0 + i * 4 + 1) * AT_PAD + r] = vv.y;
                Vs[(c0 + i * 4 + 2) * AT_PAD + r] = vv.z;
                Vs[(c0 + i * 4 + 3) * AT_PAD + r] = vv.w;
            }
        }
        __syncthreads();   // K/V visible, Q visible (first iter)

        // S = Q K^T : lane owns keys {2*lane, 2*lane+1}, warp owns 8 q rows
        float s[8][2];
#pragma unroll
        for (int r = 0; r < 8; r++) { s[r][0] = 0.f; s[r][1] = 0.f; }
#pragma unroll 8
        for (int d = 0; d < 64; d++) {
            float4 qa = *(const float4*)&Qs[d * AT_PAD + qr];
            float4 qb = *(const float4*)&Qs[d * AT_PAD + qr + 4];
            float2 kk = *(const float2*)&KPs[d * AT_PAD + 2 * lane];
            s[0][0] += qa.x * kk.x; s[0][1] += qa.x * kk.y;
            s[1][0] += qa.y * kk.x; s[1][1] += qa.y * kk.y;
            s[2][0] += qa.z * kk.x; s[2][1] += qa.z * kk.y;
            s[3][0] += qa.w * kk.x; s[3][1] += qa.w * kk.y;
            s[4][0] += qb.x * kk.x; s[4][1] += qb.x * kk.y;
            s[5][0] += qb.y * kk.x; s[5][1] += qb.y * kk.y;
            s[6][0] += qb.z * kk.x; s[6][1] += qb.z * kk.y;
            s[7][0] += qb.w * kk.x; s[7][1] += qb.w * kk.y;
        }

        // streaming softmax update
#pragma unroll
        for (int r = 0; r < 8; r++) {
            float tmax = fmaxf(s[r][0], s[r][1]);
#pragma unroll
            for (int o = 16; o; o >>= 1) tmax = fmaxf(tmax, __shfl_xor_sync(0xffffffffu, tmax, o));
            float mn = fmaxf(m[r], tmax);
            float corr = __expf(m[r] - mn);
            float p0 = __expf(s[r][0] - mn);
            float p1 = __expf(s[r][1] - mn);
            float rs = p0 + p1;
#pragma unroll
            for (int o = 16; o; o >>= 1) rs += __shfl_xor_sync(0xffffffffu, rs, o);
            l[r] = l[r] * corr + rs;
            m[r] = mn;
            o0[r] *= corr; o1[r] *= corr;
            s[r][0] = p0; s[r][1] = p1;
        }
        __syncthreads();   // all warps done reading KPs as Ks

        // write P (q-major): KPs[q][k]
#pragma unroll
        for (int r = 0; r < 8; r++)
            *(float2*)&KPs[(qr + r) * AT_PAD + 2 * lane] = make_float2(s[r][0], s[r][1]);
        __syncthreads();

        // O += P V : lane owns d = lane and lane+32
        const float* vr0 = &Vs[lane * AT_PAD];
        const float* vr1 = &Vs[(lane + 32) * AT_PAD];
#pragma unroll 4
        for (int k4 = 0; k4 < 16; k4++) {
            float4 v0 = *(const float4*)(vr0 + 4 * k4);
            float4 v1 = *(const float4*)(vr1 + 4 * k4);
#pragma unroll
            for (int r = 0; r < 8; r++) {
                float4 p = *(const float4*)&KPs[(qr + r) * AT_PAD + 4 * k4];
                o0[r] += p.x * v0.x + p.y * v0.y + p.z * v0.z + p.w * v0.w;
                o1[r] += p.x * v1.x + p.y * v1.y + p.z * v1.z + p.w * v1.w;
            }
        }
    }

    // epilogue: normalize + store
#pragma unroll
    for (int r = 0; r < 8; r++) {
        float inv = 1.0f / l[r];
        int t = b * Sd + q0 + qr + r;
        g_attno[(size_t)t * Dm + h * HDd + lane] = o0[r] * inv;
        g_attno[(size_t)t * Dm + h * HDd + lane + 32] = o1[r] * inv;
    }
}

// ---------------- 8. fused residual + LN1 + residual + LN2 ----------------
__global__ void ln_k(const float* __restrict__ x,
                     const float* __restrict__ ln1w, const float* __restrict__ ln1b,
                     const float* __restrict__ ln2w, const float* __restrict__ ln2b,
                     float* __restrict__ out) {
    int t = blockIdx.x, tid = threadIdx.x;  // 256 threads, 2 elems each
    __shared__ float r1[8], r2[8];
    __shared__ float mu_s, rs_s;
    size_t off = (size_t)t * Dm;
    float a0 = x[off + tid] + g_attnout[off + tid];
    float a1 = x[off + 256 + tid] + g_attnout[off + 256 + tid];
    float s = a0 + a1, ss = a0 * a0 + a1 * a1;
#pragma unroll
    for (int o = 16; o; o >>= 1) {
        s += __shfl_xor_sync(0xffffffffu, s, o);
        ss += __shfl_xor_sync(0xffffffffu, ss, o);
    }
    if ((tid & 31) == 0) { r1[tid >> 5] = s; r2[tid >> 5] = ss; }
    __syncthreads();
    if (tid == 0) {
        float S = 0.f, SS = 0.f;
#pragma unroll
        for (int i = 0; i < 8; i++) { S += r1[i]; SS += r2[i]; }
        float mu = S * (1.0f / 512.0f);
        mu_s = mu;
        rs_s = rsqrtf(SS * (1.0f / 512.0f) - mu * mu + 1e-5f);
    }
    __syncthreads();
    float mu = mu_s, rs = rs_s;
    float z0 = (a0 - mu) * rs * ln1w[tid] + ln1b[tid] + g_nout[off + tid];
    float z1 = (a1 - mu) * rs * ln1w[256 + tid] + ln1b[256 + tid] + g_nout[off + 256 + tid];
    s = z0 + z1; ss = z0 * z0 + z1 * z1;
#pragma unroll
    for (int o = 16; o; o >>= 1) {
        s += __shfl_xor_sync(0xffffffffu, s, o);
        ss += __shfl_xor_sync(0xffffffffu, ss, o);
    }
    __syncthreads();
    if ((tid & 31) == 0) { r1[tid >> 5] = s; r2[tid >> 5] = ss; }
    __syncthreads();
    if (tid == 0) {
        float S = 0.f, SS = 0.f;
#pragma unroll
        for (int i = 0; i < 8; i++) { S += r1[i]; SS += r2[i]; }
        float mu2 = S * (1.0f / 512.0f);
        mu_s = mu2;
        rs_s = rsqrtf(SS * (1.0f / 512.0f) - mu2 * mu2 + 1e-5f);
    }
    __syncthreads();
    mu = mu_s; rs = rs_s;
    out[off + tid] = (z0 - mu) * rs * ln2w[tid] + ln2b[tid];
    out[off + 256 + tid] = (z1 - mu) * rs * ln2w[256 + tid] + ln2b[256 + tid];
}

// ---------------- launcher ----------------
extern "C" void kernel_launch(void* const* d_in, const int* in_sizes, int n_in,
                              void* d_out, int out_size) {
    const float* x    = (const float*)d_in[0];
    const float* Wr   = (const float*)d_in[1];
    const float* br   = (const float*)d_in[2];
    const float* W1   = (const float*)d_in[3];
    const float* b1   = (const float*)d_in[4];
    const float* W2   = (const float*)d_in[5];
    const float* b2   = (const float*)d_in[6];
    const float* Wqkv = (const float*)d_in[7];
    const float* bqkv = (const float*)d_in[8];
    const float* Wo   = (const float*)d_in[9];
    const float* bo   = (const float*)d_in[10];
    const float* ln1w = (const float*)d_in[11];
    const float* ln1b = (const float*)d_in[12];
    const float* ln2w = (const float*)d_in[13];
    const float* ln2b = (const float*)d_in[14];
    float* out = (float*)d_out;

    float *p_nout, *p_qkv, *p_attno, *p_attnout, *p_wqkvt, *p_wot;
    cudaGetSymbolAddress((void**)&p_nout, g_nout);
    cudaGetSymbolAddress((void**)&p_qkv, g_qkv);
    cudaGetSymbolAddress((void**)&p_attno, g_attno);
    cudaGetSymbolAddress((void**)&p_attnout, g_attnout);
    cudaGetSymbolAddress((void**)&p_wqkvt, g_WqkvT);
    cudaGetSymbolAddress((void**)&p_wot, g_WoT);

    static int attn_attr_set = 0;
    if (!attn_attr_set) {
        cudaFuncSetAttribute(attn2_k, cudaFuncAttributeMaxDynamicSharedMemorySize, SMEM_ATTN);
        attn_attr_set = 1;
    }

    // router + list build
    router_k<<<T / 8, 256>>>(x, Wr, br);
    zero_k<<<1, 32>>>();
    build_k<<<(T * Kk + 255) / 256, 256>>>();

    // sparse FFN (only selected neuron-token pairs), pipelined FFMA2 GEMMs
    ffn1_k<<<dim3(16, 32, 32), 128>>>(x, W1, b1);
    ffn2_k<<<dim3(4, 32, 32), 128>>>(W2, b2);
    reduce_k<<<(T * Dm / 4 + 255) / 256, 256>>>();

    // attention
    transpose_k<<<dim3(16, 48), dim3(32, 8)>>>(Wqkv, p_wqkvt, D3, Dm);
    transpose_k<<<dim3(16, 16), dim3(32, 8)>>>(Wo, p_wot, Dm, Dm);
    gemm_k<<<dim3(D3 / 128, T / 64), 128>>>(p_nout, p_wqkvt, bqkv, p_qkv, D3);
    attn2_k<<<dim3(Sd / 64, NHd, Bd), 256, SMEM_ATTN>>>();
    gemm_k<<<dim3(Dm / 128, T / 64), 128>>>(p_attno, p_wot, bo, p_attnout, Dm);

    // epilogue
    ln_k<<<T, 256>>>(x, ln1w, ln1b, ln2w, ln2b, out);
}

// round 6
// speedup vs baseline: 3.3542x; 1.4885x over previous
#include <cuda_runtime.h>
#include <cuda_bf16.h>
#include <math.h>
#include <stdint.h>

#define T   2048
#define Dm  512
#define Np  32
#define Hd  2048
#define Kk  4
#define NHd 8
#define HDd 64
#define Sd  1024
#define Bd  2
#define D3  1536

#define RPAD 132
#define KTILE_FLOATS (16 * RPAD)
#define AT_PAD 68
#define AT_REG (64 * AT_PAD)
#define SMEM_ATTN (3 * AT_REG * 4)

// HMMA FFN tile constants: pitch 72 bf16 per row, 128 rows per tile
#define FP 72
#define FTILE (128 * FP)               // bf16 units per tile
#define SMEM_FFN (4 * FTILE * 2)       // bytes: 2 bufs x (A + B)

__device__ int   g_idx[T * Kk];
__device__ int   g_cnt[Np];
__device__ int   g_list[Np * T];
__device__ float g_pairs[T * Kk * Dm];
__device__ float g_nout[T * Dm];
__device__ float g_qkv[T * D3];
__device__ float g_attno[T * Dm];
__device__ float g_attnout[T * Dm];
__device__ float g_WqkvT[Dm * D3];
__device__ float g_WoT[Dm * Dm];
__device__ __nv_bfloat16 g_x3[T * 2 * Dm];                 // [t][xh(512)|xl(512)]
__device__ __nv_bfloat16 g_W13[(size_t)Np * Hd * 2 * Dm];  // [n][h][Wh(512)|Wl(512)]
__device__ __nv_bfloat16 g_W23[(size_t)Np * Dm * 2 * Hd];  // [n][d][Wh(2048)|Wl(2048)]
__device__ __nv_bfloat16 g_h3[(size_t)T * Kk * 2 * Hd];    // [pair][hh(2048)|hl(2048)]

__device__ __forceinline__ float gelu_f(float v) {
    float u = 0.7978845608028654f * (v + 0.044715f * v * v * v);
    return 0.5f * v * (1.0f + tanhf(u));
}
__device__ __forceinline__ unsigned long long ffma2(unsigned long long a,
                                                    unsigned long long b,
                                                    unsigned long long c) {
    unsigned long long d;
    asm("fma.rn.f32x2 %0, %1, %2, %3;" : "=l"(d) : "l"(a), "l"(b), "l"(c));
    return d;
}
union U2 { unsigned long long u; float2 f; };

__device__ __forceinline__ void mma_bf16(float c[4], uint32_t a0, uint32_t a1,
                                         uint32_t a2, uint32_t a3,
                                         uint32_t b0, uint32_t b1) {
    asm volatile(
        "mma.sync.aligned.m16n8k16.row.col.f32.bf16.bf16.f32 "
        "{%0,%1,%2,%3}, {%4,%5,%6,%7}, {%8,%9}, {%0,%1,%2,%3};"
        : "+f"(c[0]), "+f"(c[1]), "+f"(c[2]), "+f"(c[3])
        : "r"(a0), "r"(a1), "r"(a2), "r"(a3), "r"(b0), "r"(b1));
}

// ---------------- router / list ----------------
__global__ void router_k(const float* __restrict__ x, const float* __restrict__ Wr,
                         const float* __restrict__ br) {
    int warp = threadIdx.x >> 5, lane = threadIdx.x & 31;
    int t = blockIdx.x * 8 + warp;
    const float* xp = x + (size_t)t * Dm + lane * 16;
    float4 xv[4];
#pragma unroll
    for (int i = 0; i < 4; i++) xv[i] = *(const float4*)(xp + i * 4);
    float lg[32];
#pragma unroll 1
    for (int n = 0; n < 32; n++) {
        const float* wp = Wr + n * Dm + lane * 16;
        float acc = 0.f;
#pragma unroll
        for (int i = 0; i < 4; i++) {
            float4 w = *(const float4*)(wp + i * 4);
            acc += xv[i].x * w.x + xv[i].y * w.y + xv[i].z * w.z + xv[i].w * w.w;
        }
#pragma unroll
        for (int o = 16; o; o >>= 1) acc += __shfl_xor_sync(0xffffffffu, acc, o);
        lg[n] = acc + br[n];
    }
    if (lane == 0) {
        unsigned used = 0;
        for (int k2 = 0; k2 < 4; k2++) {
            float best = -1e30f; int bi = 0;
            for (int n = 0; n < 32; n++)
                if (!((used >> n) & 1u) && lg[n] > best) { best = lg[n]; bi = n; }
            used |= 1u << bi;
            g_idx[t * 4 + k2] = bi;
        }
    }
}
__global__ void zero_k() { if (threadIdx.x < Np) g_cnt[threadIdx.x] = 0; }
__global__ void build_k() {
    int e = blockIdx.x * 256 + threadIdx.x;
    if (e >= T * Kk) return;
    int n = g_idx[e];
    int pos = atomicAdd(&g_cnt[n], 1);
    g_list[n * T + pos] = e;
}

// ---------------- bf16 split conversions ----------------
__global__ void convx3_k(const float* __restrict__ x) {
    int i = blockIdx.x * 256 + threadIdx.x;
    int t = i >> 9, d = i & 511;
    float v = x[i];
    __nv_bfloat16 hi = __float2bfloat16(v);
    __nv_bfloat16 lo = __float2bfloat16(v - __bfloat162float(hi));
    g_x3[(size_t)t * 1024 + d] = hi;
    g_x3[(size_t)t * 1024 + 512 + d] = lo;
}
// W[n][Kd][Nd] fp32 -> W3[n][Nd][2*Kd] bf16 (hi|lo)
__global__ void convw_k(const float* __restrict__ W, __nv_bfloat16* __restrict__ W3,
                        int Kd, int Nd) {
    __shared__ float tile[32][33];
    int n = blockIdx.z, k0 = blockIdx.y * 32, c0 = blockIdx.x * 32;
    const float* Wn = W + (size_t)n * Kd * Nd;
#pragma unroll
    for (int i = 0; i < 32; i += 8)
        tile[threadIdx.y + i][threadIdx.x] = Wn[(size_t)(k0 + threadIdx.y + i) * Nd + c0 + threadIdx.x];
    __syncthreads();
    __nv_bfloat16* Wo = W3 + (size_t)n * Nd * 2 * Kd;
#pragma unroll
    for (int i = 0; i < 32; i += 8) {
        float v = tile[threadIdx.x][threadIdx.y + i];
        __nv_bfloat16 hi = __float2bfloat16(v);
        __nv_bfloat16 lo = __float2bfloat16(v - __bfloat162float(hi));
        size_t ro = (size_t)(c0 + threadIdx.y + i) * 2 * Kd + k0 + threadIdx.x;
        Wo[ro] = hi;
        Wo[ro + Kd] = lo;
    }
}

// ---------------- FFN pass 1 (HMMA mma.sync): h = gelu(x @ W1 + b1) ----------------
// grid (16 n-chunks, 16 m-tiles, 32 neurons), 256 thr (8 warps, 2M x 4N).
// K-extended: 3 segments x 512 (xh*Wh, xh*Wl, xl*Wh). Chunks of k64.
__global__ __launch_bounds__(256)
void ffn1_mma_k(const float* __restrict__ b1) {
    int n = blockIdx.z, mt0 = blockIdx.y, nb = blockIdx.x * 128;
    int cnt = g_cnt[n];
    int base = mt0 * 128;
    if (base >= cnt) return;

    extern __shared__ __align__(16) __nv_bfloat16 sm[];
    __shared__ int es[128];
    int tid = threadIdx.x, wid = tid >> 5, lane = tid & 31;
    if (tid < 128) es[tid] = (base + tid < cnt) ? g_list[n * T + base + tid] : -1;
    __syncthreads();

    int hr = tid >> 1, half = tid & 1;
    int e_row = es[hr];
    const __nv_bfloat16* arow = (e_row >= 0) ? (g_x3 + (size_t)(e_row >> 2) * 1024) : 0;
    const __nv_bfloat16* brow = g_W13 + ((size_t)n * Hd + nb + hr) * 1024;
    int sto = hr * FP + half * 32;   // smem store offset (bf16 units)

    float acc[4][4][4];
#pragma unroll
    for (int i = 0; i < 4; i++)
#pragma unroll
        for (int j = 0; j < 4; j++)
#pragma unroll
            for (int k = 0; k < 4; k++) acc[i][j][k] = 0.f;

    int g = lane >> 2, t2 = (lane & 3) * 2;
    int warpM = (wid >> 2) * 64, warpN = (wid & 3) * 32;

    const int NCH = 24;
    uint4 ra[4], rb[4];
    // prologue: chunk 0 (A hi, B hi, kc=0)
    if (arow) {
#pragma unroll
        for (int i = 0; i < 4; i++) ra[i] = *(const uint4*)(arow + half * 32 + i * 8);
    } else {
#pragma unroll
        for (int i = 0; i < 4; i++) ra[i] = make_uint4(0, 0, 0, 0);
    }
#pragma unroll
    for (int i = 0; i < 4; i++) rb[i] = *(const uint4*)(brow + half * 32 + i * 8);
#pragma unroll
    for (int i = 0; i < 4; i++) {
        *(uint4*)(sm + sto + i * 8) = ra[i];
        *(uint4*)(sm + FTILE + sto + i * 8) = rb[i];
    }
    __syncthreads();

#pragma unroll 1
    for (int c = 0; c < NCH; c++) {
        int buf = c & 1;
        if (c + 1 < NCH) {
            int c1 = c + 1;
            int kc = c1 & 7;
            int sA = (c1 < 16) ? 0 : 512;
            int sB = (c1 >= 8 && c1 < 16) ? 512 : 0;
            if (arow) {
                const __nv_bfloat16* ap = arow + sA + kc * 64 + half * 32;
#pragma unroll
                for (int i = 0; i < 4; i++) ra[i] = *(const uint4*)(ap + i * 8);
            }
            const __nv_bfloat16* bp = brow + sB + kc * 64 + half * 32;
#pragma unroll
            for (int i = 0; i < 4; i++) rb[i] = *(const uint4*)(bp + i * 8);
        }
        // compute on buf
        const __nv_bfloat16* As = sm + buf * 2 * FTILE;
        const __nv_bfloat16* Bs = As + FTILE;
#pragma unroll
        for (int kk = 0; kk < 4; kk++) {
            int kb = kk * 16 + t2;
            uint32_t af[4][4], bf[4][2];
#pragma unroll
            for (int mt = 0; mt < 4; mt++) {
                int r = warpM + mt * 16 + g;
                af[mt][0] = *(const uint32_t*)(As + r * FP + kb);
                af[mt][1] = *(const uint32_t*)(As + (r + 8) * FP + kb);
                af[mt][2] = *(const uint32_t*)(As + r * FP + kb + 8);
                af[mt][3] = *(const uint32_t*)(As + (r + 8) * FP + kb + 8);
            }
#pragma unroll
            for (int nt = 0; nt < 4; nt++) {
                int r = warpN + nt * 8 + g;
                bf[nt][0] = *(const uint32_t*)(Bs + r * FP + kb);
                bf[nt][1] = *(const uint32_t*)(Bs + r * FP + kb + 8);
            }
#pragma unroll
            for (int mt = 0; mt < 4; mt++)
#pragma unroll
                for (int nt = 0; nt < 4; nt++)
                    mma_bf16(acc[mt][nt], af[mt][0], af[mt][1], af[mt][2], af[mt][3],
                             bf[nt][0], bf[nt][1]);
        }
        if (c + 1 < NCH) {
            __nv_bfloat16* d = sm + ((c + 1) & 1) * 2 * FTILE;
#pragma unroll
            for (int i = 0; i < 4; i++) {
                *(uint4*)(d + sto + i * 8) = ra[i];
                *(uint4*)(d + FTILE + sto + i * 8) = rb[i];
            }
        }
        __syncthreads();
    }

    // epilogue: bias + gelu + bf16 hi/lo split -> g_h3
#pragma unroll
    for (int mt = 0; mt < 4; mt++) {
#pragma unroll
        for (int rr = 0; rr < 2; rr++) {
            int row = warpM + mt * 16 + g + rr * 8;
            int er = es[row];
            if (er < 0) continue;
            __nv_bfloat16* hp = g_h3 + (size_t)er * 4096;
#pragma unroll
            for (int nt = 0; nt < 4; nt++) {
                int col = nb + warpN + nt * 8 + t2;
                float v0 = gelu_f(acc[mt][nt][rr * 2 + 0] + b1[(size_t)n * Hd + col]);
                float v1 = gelu_f(acc[mt][nt][rr * 2 + 1] + b1[(size_t)n * Hd + col + 1]);
                __nv_bfloat16 h0 = __float2bfloat16(v0), h1 = __float2bfloat16(v1);
                __nv_bfloat16 l0 = __float2bfloat16(v0 - __bfloat162float(h0));
                __nv_bfloat16 l1 = __float2bfloat16(v1 - __bfloat162float(h1));
                uint32_t hp2 = (uint32_t)__bfloat16_as_ushort(h0) | ((uint32_t)__bfloat16_as_ushort(h1) << 16);
                uint32_t lp2 = (uint32_t)__bfloat16_as_ushort(l0) | ((uint32_t)__bfloat16_as_ushort(l1) << 16);
                *(uint32_t*)(hp + col) = hp2;
                *(uint32_t*)(hp + 2048 + col) = lp2;
            }
        }
    }
}

// ---------------- FFN pass 2 (HMMA mma.sync): out = h @ W2 + b2 ----------------
// grid (4 n-chunks, 16 m-tiles, 32 neurons), 256 thr. K-extended: 3 x 2048.
__global__ __launch_bounds__(256)
void ffn2_mma_k(const float* __restrict__ b2) {
    int n = blockIdx.z, mt0 = blockIdx.y, nb = blockIdx.x * 128;
    int cnt = g_cnt[n];
    int base = mt0 * 128;
    if (base >= cnt) return;

    extern __shared__ __align__(16) __nv_bfloat16 sm[];
    __shared__ int es[128];
    int tid = threadIdx.x, wid = tid >> 5, lane = tid & 31;
    if (tid < 128) es[tid] = (base + tid < cnt) ? g_list[n * T + base + tid] : -1;
    __syncthreads();

    int hr = tid >> 1, half = tid & 1;
    int e_row = es[hr];
    const __nv_bfloat16* arow = (e_row >= 0) ? (g_h3 + (size_t)e_row * 4096) : 0;
    const __nv_bfloat16* brow = g_W23 + ((size_t)n * Dm + nb + hr) * 4096;
    int sto = hr * FP + half * 32;

    float acc[4][4][4];
#pragma unroll
    for (int i = 0; i < 4; i++)
#pragma unroll
        for (int j = 0; j < 4; j++)
#pragma unroll
            for (int k = 0; k < 4; k++) acc[i][j][k] = 0.f;

    int g = lane >> 2, t2 = (lane & 3) * 2;
    int warpM = (wid >> 2) * 64, warpN = (wid & 3) * 32;

    const int NCH = 96;
    uint4 ra[4], rb[4];
    if (arow) {
#pragma unroll
        for (int i = 0; i < 4; i++) ra[i] = *(const uint4*)(arow + half * 32 + i * 8);
    } else {
#pragma unroll
        for (int i = 0; i < 4; i++) ra[i] = make_uint4(0, 0, 0, 0);
    }
#pragma unroll
    for (int i = 0; i < 4; i++) rb[i] = *(const uint4*)(brow + half * 32 + i * 8);
#pragma unroll
    for (int i = 0; i < 4; i++) {
        *(uint4*)(sm + sto + i * 8) = ra[i];
        *(uint4*)(sm + FTILE + sto + i * 8) = rb[i];
    }
    __syncthreads();

#pragma unroll 1
    for (int c = 0; c < NCH; c++) {
        int buf = c & 1;
        if (c + 1 < NCH) {
            int c1 = c + 1;
            int kc = c1 & 31;
            int sA = (c1 < 64) ? 0 : 2048;
            int sB = (c1 >= 32 && c1 < 64) ? 2048 : 0;
            if (arow) {
                const __nv_bfloat16* ap = arow + sA + kc * 64 + half * 32;
#pragma unroll
                for (int i = 0; i < 4; i++) ra[i] = *(const uint4*)(ap + i * 8);
            }
            const __nv_bfloat16* bp = brow + sB + kc * 64 + half * 32;
#pragma unroll
            for (int i = 0; i < 4; i++) rb[i] = *(const uint4*)(bp + i * 8);
        }
        const __nv_bfloat16* As = sm + buf * 2 * FTILE;
        const __nv_bfloat16* Bs = As + FTILE;
#pragma unroll
        for (int kk = 0; kk < 4; kk++) {
            int kb = kk * 16 + t2;
            uint32_t af[4][4], bf[4][2];
#pragma unroll
            for (int mt = 0; mt < 4; mt++) {
                int r = warpM + mt * 16 + g;
                af[mt][0] = *(const uint32_t*)(As + r * FP + kb);
                af[mt][1] = *(const uint32_t*)(As + (r + 8) * FP + kb);
                af[mt][2] = *(const uint32_t*)(As + r * FP + kb + 8);
                af[mt][3] = *(const uint32_t*)(As + (r + 8) * FP + kb + 8);
            }
#pragma unroll
            for (int nt = 0; nt < 4; nt++) {
                int r = warpN + nt * 8 + g;
                bf[nt][0] = *(const uint32_t*)(Bs + r * FP + kb);
                bf[nt][1] = *(const uint32_t*)(Bs + r * FP + kb + 8);
            }
#pragma unroll
            for (int mt = 0; mt < 4; mt++)
#pragma unroll
                for (int nt = 0; nt < 4; nt++)
                    mma_bf16(acc[mt][nt], af[mt][0], af[mt][1], af[mt][2], af[mt][3],
                             bf[nt][0], bf[nt][1]);
        }
        if (c + 1 < NCH) {
            __nv_bfloat16* d = sm + ((c + 1) & 1) * 2 * FTILE;
#pragma unroll
            for (int i = 0; i < 4; i++) {
                *(uint4*)(d + sto + i * 8) = ra[i];
                *(uint4*)(d + FTILE + sto + i * 8) = rb[i];
            }
        }
        __syncthreads();
    }

#pragma unroll
    for (int mt = 0; mt < 4; mt++) {
#pragma unroll
        for (int rr = 0; rr < 2; rr++) {
            int row = warpM + mt * 16 + g + rr * 8;
            int er = es[row];
            if (er < 0) continue;
            float* op = g_pairs + (size_t)er * Dm;
#pragma unroll
            for (int nt = 0; nt < 4; nt++) {
                int col = nb + warpN + nt * 8 + t2;
                float2 o;
                o.x = acc[mt][nt][rr * 2 + 0] + b2[(size_t)n * Dm + col];
                o.y = acc[mt][nt][rr * 2 + 1] + b2[(size_t)n * Dm + col + 1];
                *(float2*)(op + col) = o;
            }
        }
    }
}

// ---------------- mean over k ----------------
__global__ void reduce_k() {
    int id = blockIdx.x * 256 + threadIdx.x;
    if (id >= T * Dm / 4) return;
    int t = id >> 7, c4 = (id & 127) << 2;
    float4 s = make_float4(0.f, 0.f, 0.f, 0.f);
#pragma unroll
    for (int k2 = 0; k2 < 4; k2++) {
        float4 v = *(const float4*)&g_pairs[(size_t)(t * 4 + k2) * Dm + c4];
        s.x += v.x; s.y += v.y; s.z += v.z; s.w += v.w;
    }
    s.x *= 0.25f; s.y *= 0.25f; s.z *= 0.25f; s.w *= 0.25f;
    *(float4*)&g_nout[(size_t)t * Dm + c4] = s;
}

// ---------------- fp32 transpose ----------------
__global__ void transpose_k(const float* __restrict__ W, float* __restrict__ WT,
                            int R, int C) {
    __shared__ float tile[32][33];
    int r0 = blockIdx.y * 32, c0 = blockIdx.x * 32;
    int r = r0 + threadIdx.y, c = c0 + threadIdx.x;
#pragma unroll
    for (int i = 0; i < 32; i += 8)
        if (r + i < R && c < C) tile[threadIdx.y + i][threadIdx.x] = W[(size_t)(r + i) * C + c];
    __syncthreads();
    int rt = c0 + threadIdx.y, ct = r0 + threadIdx.x;
#pragma unroll
    for (int i = 0; i < 32; i += 8)
        if (rt + i < C && ct < R) WT[(size_t)(rt + i) * R + ct] = tile[threadIdx.x][threadIdx.y + i];
}

// ---------------- dense GEMM (FFMA2) ----------------
__device__ __forceinline__ void mainloop16d(const float* __restrict__ asd,
                                            const float* __restrict__ bsk,
                                            int m0, int n0,
                                            unsigned long long acc[32]) {
#pragma unroll
    for (int k = 0; k < 16; k++) {
        const ulonglong2* apq = (const ulonglong2*)(asd + k * RPAD + 2 * m0);
        ulonglong2 aP0 = apq[0], aP1 = apq[1], aP2 = apq[2], aP3 = apq[3];
        const ulonglong2* bp = (const ulonglong2*)(bsk + k * RPAD + n0);
        ulonglong2 bA = bp[0], bB = bp[1];
        unsigned long long a[8] = {aP0.x, aP0.y, aP1.x, aP1.y, aP2.x, aP2.y, aP3.x, aP3.y};
#pragma unroll
        for (int r = 0; r < 8; r++) {
            acc[r * 4 + 0] = ffma2(a[r], bA.x, acc[r * 4 + 0]);
            acc[r * 4 + 1] = ffma2(a[r], bA.y, acc[r * 4 + 1]);
            acc[r * 4 + 2] = ffma2(a[r], bB.x, acc[r * 4 + 2]);
            acc[r * 4 + 3] = ffma2(a[r], bB.y, acc[r * 4 + 3]);
        }
    }
}
__device__ __forceinline__ void store_dupA_k(float* ad, float4 a0, float4 a1) {
    *(float2*)(ad + 0 * RPAD) = make_float2(a0.x, a0.x);
    *(float2*)(ad + 1 * RPAD) = make_float2(a0.y, a0.y);
    *(float2*)(ad + 2 * RPAD) = make_float2(a0.z, a0.z);
    *(float2*)(ad + 3 * RPAD) = make_float2(a0.w, a0.w);
    *(float2*)(ad + 4 * RPAD) = make_float2(a1.x, a1.x);
    *(float2*)(ad + 5 * RPAD) = make_float2(a1.y, a1.y);
    *(float2*)(ad + 6 * RPAD) = make_float2(a1.z, a1.z);
    *(float2*)(ad + 7 * RPAD) = make_float2(a1.w, a1.w);
}
__device__ __forceinline__ void store_B_k(float* bd, float4 w0, float4 w1, float4 w2, float4 w3) {
    *(float4*)(bd + 0) = w0; *(float4*)(bd + 4) = w1;
    *(float4*)(bd + 8) = w2; *(float4*)(bd + 12) = w3;
}
__global__ __launch_bounds__(128, 3)
void gemm_k(const float* __restrict__ A, const float* __restrict__ WT,
            const float* __restrict__ bias, float* __restrict__ C, int Nc) {
    int nb = blockIdx.x * 128, mg = blockIdx.y * 64;
    __shared__ __align__(16) float asd[2 * KTILE_FLOATS];
    __shared__ __align__(16) float bsk[2 * KTILE_FLOATS];
    int tid = threadIdx.x;
    int tx = tid & 15, ty = tid >> 4, m0 = ty * 8, n0 = tx * 8;
    unsigned long long acc[32];
#pragma unroll
    for (int i = 0; i < 32; i++) acc[i] = 0ull;
    int arow = tid >> 1, kh = (tid & 1) * 8;
    const float* aptr = A + (size_t)(mg + arow) * Dm + kh;
    int brow = tid >> 3, bcol = (tid & 7) * 16;
    const float* wbase = WT + nb + (size_t)brow * Nc + bcol;
    float4 a0 = *(const float4*)(aptr), a1 = *(const float4*)(aptr + 4);
    float4 w0 = *(const float4*)(wbase),     w1 = *(const float4*)(wbase + 4);
    float4 w2 = *(const float4*)(wbase + 8), w3 = *(const float4*)(wbase + 12);
    store_dupA_k(asd + kh * RPAD + 2 * arow, a0, a1);
    store_B_k(bsk + brow * RPAD + bcol, w0, w1, w2, w3);
    __syncthreads();
    const int NIT = Dm / 16;
#pragma unroll 1
    for (int it = 0; it < NIT; it++) {
        int buf = it & 1;
        if (it + 1 < NIT) {
            int k0 = (it + 1) * 16;
            a0 = *(const float4*)(aptr + k0); a1 = *(const float4*)(aptr + k0 + 4);
            const float* wp = wbase + (size_t)k0 * Nc;
            w0 = *(const float4*)(wp);     w1 = *(const float4*)(wp + 4);
            w2 = *(const float4*)(wp + 8); w3 = *(const float4*)(wp + 12);
        }
        mainloop16d(asd + buf * KTILE_FLOATS, bsk + buf * KTILE_FLOATS, m0, n0, acc);
        if (it + 1 < NIT) {
            int b2i = (it + 1) & 1;
            store_dupA_k(asd + b2i * KTILE_FLOATS + kh * RPAD + 2 * arow, a0, a1);
            store_B_k(bsk + b2i * KTILE_FLOATS + brow * RPAD + bcol, w0, w1, w2, w3);
        }
        __syncthreads();
    }
    int col = nb + n0;
    float4 bb0 = *(const float4*)&bias[col];
    float4 bb1 = *(const float4*)&bias[col + 4];
#pragma unroll
    for (int r = 0; r < 8; r++) {
        U2 p0, p1, p2, p3;
        p0.u = acc[r * 4 + 0]; p1.u = acc[r * 4 + 1];
        p2.u = acc[r * 4 + 2]; p3.u = acc[r * 4 + 3];
        float4 o0 = make_float4(p0.f.x + bb0.x, p0.f.y + bb0.y, p1.f.x + bb0.z, p1.f.y + bb0.w);
        float4 o1 = make_float4(p2.f.x + bb1.x, p2.f.y + bb1.y, p3.f.x + bb1.z, p3.f.y + bb1.w);
        float* op = &C[(size_t)(mg + m0 + r) * Nc + col];
        *(float4*)op = o0;
        *(float4*)(op + 4) = o1;
    }
}

// ---------------- attention (flash, q-tile 64) ----------------
__global__ __launch_bounds__(256)
void attn2_k() {
    extern __shared__ float smf[];
    float* Qs  = smf;
    float* KPs = smf + AT_REG;
    float* Vs  = smf + 2 * AT_REG;
    int q0 = blockIdx.x * 64, h = blockIdx.y, b = blockIdx.z;
    int tid = threadIdx.x, lane = tid & 31, w = tid >> 5;
    int qr = w * 8;
    {
        int r = tid >> 2, c0 = (tid & 3) * 16;
        const float* qp = g_qkv + (size_t)(b * Sd + q0 + r) * D3 + h * HDd + c0;
#pragma unroll
        for (int i = 0; i < 4; i++) {
            float4 v = *(const float4*)(qp + i * 4);
            Qs[(c0 + i * 4 + 0) * AT_PAD + r] = v.x * 0.125f;
            Qs[(c0 + i * 4 + 1) * AT_PAD + r] = v.y * 0.125f;
            Qs[(c0 + i * 4 + 2) * AT_PAD + r] = v.z * 0.125f;
            Qs[(c0 + i * 4 + 3) * AT_PAD + r] = v.w * 0.125f;
        }
    }
    float m[8], l[8], o0[8], o1[8];
#pragma unroll
    for (int r = 0; r < 8; r++) { m[r] = -1e30f; l[r] = 0.f; o0[r] = 0.f; o1[r] = 0.f; }
#pragma unroll 1
    for (int j0 = 0; j0 < Sd; j0 += 64) {
        __syncthreads();
        {
            int r = tid >> 2, c0 = (tid & 3) * 16;
            const float* kp = g_qkv + (size_t)(b * Sd + j0 + r) * D3 + Dm + h * HDd + c0;
            const float* vp = kp + Dm;
#pragma unroll
            for (int i = 0; i < 4; i++) {
                float4 kv = *(const float4*)(kp + i * 4);
                KPs[(c0 + i * 4 + 0) * AT_PAD + r] = kv.x;
                KPs[(c0 + i * 4 + 1) * AT_PAD + r] = kv.y;
                KPs[(c0 + i * 4 + 2) * AT_PAD + r] = kv.z;
                KPs[(c0 + i * 4 + 3) * AT_PAD + r] = kv.w;
                float4 vv = *(const float4*)(vp + i * 4);
                Vs[(c0 + i * 4 + 0) * AT_PAD + r] = vv.x;
                Vs[(c0 + i * 4 + 1) * AT_PAD + r] = vv.y;
                Vs[(c0 + i * 4 + 2) * AT_PAD + r] = vv.z;
                Vs[(c0 + i * 4 + 3) * AT_PAD + r] = vv.w;
            }
        }
        __syncthreads();
        float s[8][2];
#pragma unroll
        for (int r = 0; r < 8; r++) { s[r][0] = 0.f; s[r][1] = 0.f; }
#pragma unroll 8
        for (int d = 0; d < 64; d++) {
            float4 qa = *(const float4*)&Qs[d * AT_PAD + qr];
            float4 qb = *(const float4*)&Qs[d * AT_PAD + qr + 4];
            float2 kk = *(const float2*)&KPs[d * AT_PAD + 2 * lane];
            s[0][0] += qa.x * kk.x; s[0][1] += qa.x * kk.y;
            s[1][0] += qa.y * kk.x; s[1][1] += qa.y * kk.y;
            s[2][0] += qa.z * kk.x; s[2][1] += qa.z * kk.y;
            s[3][0] += qa.w * kk.x; s[3][1] += qa.w * kk.y;
            s[4][0] += qb.x * kk.x; s[4][1] += qb.x * kk.y;
            s[5][0] += qb.y * kk.x; s[5][1] += qb.y * kk.y;
            s[6][0] += qb.z * kk.x; s[6][1] += qb.z * kk.y;
            s[7][0] += qb.w * kk.x; s[7][1] += qb.w * kk.y;
        }
#pragma unroll
        for (int r = 0; r < 8; r++) {
            float tmax = fmaxf(s[r][0], s[r][1]);
#pragma unroll
            for (int o = 16; o; o >>= 1) tmax = fmaxf(tmax, __shfl_xor_sync(0xffffffffu, tmax, o));
            float mn = fmaxf(m[r], tmax);
            float corr = __expf(m[r] - mn);
            float p0 = __expf(s[r][0] - mn);
            float p1 = __expf(s[r][1] - mn);
            float rs = p0 + p1;
#pragma unroll
            for (int o = 16; o; o >>= 1) rs += __shfl_xor_sync(0xffffffffu, rs, o);
            l[r] = l[r] * corr + rs;
            m[r] = mn;
            o0[r] *= corr; o1[r] *= corr;
            s[r][0] = p0; s[r][1] = p1;
        }
        __syncthreads();
#pragma unroll
        for (int r = 0; r < 8; r++)
            *(float2*)&KPs[(qr + r) * AT_PAD + 2 * lane] = make_float2(s[r][0], s[r][1]);
        __syncthreads();
        const float* vr0 = &Vs[lane * AT_PAD];
        const float* vr1 = &Vs[(lane + 32) * AT_PAD];
#pragma unroll 4
        for (int k4 = 0; k4 < 16; k4++) {
            float4 v0 = *(const float4*)(vr0 + 4 * k4);
            float4 v1 = *(const float4*)(vr1 + 4 * k4);
#pragma unroll
            for (int r = 0; r < 8; r++) {
                float4 p = *(const float4*)&KPs[(qr + r) * AT_PAD + 4 * k4];
                o0[r] += p.x * v0.x + p.y * v0.y + p.z * v0.z + p.w * v0.w;
                o1[r] += p.x * v1.x + p.y * v1.y + p.z * v1.z + p.w * v1.w;
            }
        }
    }
#pragma unroll
    for (int r = 0; r < 8; r++) {
        float inv = 1.0f / l[r];
        int t = b * Sd + q0 + qr + r;
        g_attno[(size_t)t * Dm + h * HDd + lane] = o0[r] * inv;
        g_attno[(size_t)t * Dm + h * HDd + lane + 32] = o1[r] * inv;
    }
}

// ---------------- fused dual LN ----------------
__global__ void ln_k(const float* __restrict__ x,
                     const float* __restrict__ ln1w, const float* __restrict__ ln1b,
                     const float* __restrict__ ln2w, const float* __restrict__ ln2b,
                     float* __restrict__ out) {
    int t = blockIdx.x, tid = threadIdx.x;
    __shared__ float r1[8], r2[8];
    __shared__ float mu_s, rs_s;
    size_t off = (size_t)t * Dm;
    float a0 = x[off + tid] + g_attnout[off + tid];
    float a1 = x[off + 256 + tid] + g_attnout[off + 256 + tid];
    float s = a0 + a1, ss = a0 * a0 + a1 * a1;
#pragma unroll
    for (int o = 16; o; o >>= 1) {
        s += __shfl_xor_sync(0xffffffffu, s, o);
        ss += __shfl_xor_sync(0xffffffffu, ss, o);
    }
    if ((tid & 31) == 0) { r1[tid >> 5] = s; r2[tid >> 5] = ss; }
    __syncthreads();
    if (tid == 0) {
        float S = 0.f, SS = 0.f;
#pragma unroll
        for (int i = 0; i < 8; i++) { S += r1[i]; SS += r2[i]; }
        float mu = S * (1.0f / 512.0f);
        mu_s = mu;
        rs_s = rsqrtf(SS * (1.0f / 512.0f) - mu * mu + 1e-5f);
    }
    __syncthreads();
    float mu = mu_s, rs = rs_s;
    float z0 = (a0 - mu) * rs * ln1w[tid] + ln1b[tid] + g_nout[off + tid];
    float z1 = (a1 - mu) * rs * ln1w[256 + tid] + ln1b[256 + tid] + g_nout[off + 256 + tid];
    s = z0 + z1; ss = z0 * z0 + z1 * z1;
#pragma unroll
    for (int o = 16; o; o >>= 1) {
        s += __shfl_xor_sync(0xffffffffu, s, o);
        ss += __shfl_xor_sync(0xffffffffu, ss, o);
    }
    __syncthreads();
    if ((tid & 31) == 0) { r1[tid >> 5] = s; r2[tid >> 5] = ss; }
    __syncthreads();
    if (tid == 0) {
        float S = 0.f, SS = 0.f;
#pragma unroll
        for (int i = 0; i < 8; i++) { S += r1[i]; SS += r2[i]; }
        float mu2 = S * (1.0f / 512.0f);
        mu_s = mu2;
        rs_s = rsqrtf(SS * (1.0f / 512.0f) - mu2 * mu2 + 1e-5f);
    }
    __syncthreads();
    mu = mu_s; rs = rs_s;
    out[off + tid] = (z0 - mu) * rs * ln2w[tid] + ln2b[tid];
    out[off + 256 + tid] = (z1 - mu) * rs * ln2w[256 + tid] + ln2b[256 + tid];
}

// ---------------- launcher ----------------
extern "C" void kernel_launch(void* const* d_in, const int* in_sizes, int n_in,
                              void* d_out, int out_size) {
    const float* x    = (const float*)d_in[0];
    const float* Wr   = (const float*)d_in[1];
    const float* br   = (const float*)d_in[2];
    const float* W1   = (const float*)d_in[3];
    const float* b1   = (const float*)d_in[4];
    const float* W2   = (const float*)d_in[5];
    const float* b2   = (const float*)d_in[6];
    const float* Wqkv = (const float*)d_in[7];
    const float* bqkv = (const float*)d_in[8];
    const float* Wo   = (const float*)d_in[9];
    const float* bo   = (const float*)d_in[10];
    const float* ln1w = (const float*)d_in[11];
    const float* ln1b = (const float*)d_in[12];
    const float* ln2w = (const float*)d_in[13];
    const float* ln2b = (const float*)d_in[14];
    float* out = (float*)d_out;

    float *p_nout, *p_qkv, *p_attno, *p_attnout, *p_wqkvt, *p_wot;
    __nv_bfloat16 *p_w13, *p_w23;
    cudaGetSymbolAddress((void**)&p_nout, g_nout);
    cudaGetSymbolAddress((void**)&p_qkv, g_qkv);
    cudaGetSymbolAddress((void**)&p_attno, g_attno);
    cudaGetSymbolAddress((void**)&p_attnout, g_attnout);
    cudaGetSymbolAddress((void**)&p_wqkvt, g_WqkvT);
    cudaGetSymbolAddress((void**)&p_wot, g_WoT);
    cudaGetSymbolAddress((void**)&p_w13, g_W13);
    cudaGetSymbolAddress((void**)&p_w23, g_W23);

    static int attr_set = 0;
    if (!attr_set) {
        cudaFuncSetAttribute(attn2_k, cudaFuncAttributeMaxDynamicSharedMemorySize, SMEM_ATTN);
        cudaFuncSetAttribute(ffn1_mma_k, cudaFuncAttributeMaxDynamicSharedMemorySize, SMEM_FFN);
        cudaFuncSetAttribute(ffn2_mma_k, cudaFuncAttributeMaxDynamicSharedMemorySize, SMEM_FFN);
        attr_set = 1;
    }

    // router + list build
    router_k<<<T / 8, 256>>>(x, Wr, br);
    zero_k<<<1, 32>>>();
    build_k<<<(T * Kk + 255) / 256, 256>>>();

    // bf16 hi/lo splits
    convx3_k<<<T * Dm / 256, 256>>>(x);
    convw_k<<<dim3(Hd / 32, Dm / 32, Np), dim3(32, 8)>>>(W1, p_w13, Dm, Hd);
    convw_k<<<dim3(Dm / 32, Hd / 32, Np), dim3(32, 8)>>>(W2, p_w23, Hd, Dm);

    // sparse FFN on tensor cores (mma.sync HMMA)
    ffn1_mma_k<<<dim3(16, 16, 32), 256, SMEM_FFN>>>(b1);
    ffn2_mma_k<<<dim3(4, 16, 32), 256, SMEM_FFN>>>(b2);
    reduce_k<<<(T * Dm / 4 + 255) / 256, 256>>>();

    // attention
    transpose_k<<<dim3(16, 48), dim3(32, 8)>>>(Wqkv, p_wqkvt, D3, Dm);
    transpose_k<<<dim3(16, 16), dim3(32, 8)>>>(Wo, p_wot, Dm, Dm);
    gemm_k<<<dim3(D3 / 128, T / 64), 128>>>(p_nout, p_wqkvt, bqkv, p_qkv, D3);
    attn2_k<<<dim3(Sd / 64, NHd, Bd), 256, SMEM_ATTN>>>();
    gemm_k<<<dim3(Dm / 128, T / 64), 128>>>(p_attno, p_wot, bo, p_attnout, Dm);

    // epilogue
    ln_k<<<T, 256>>>(x, ln1w, ln1b, ln2w, ln2b, out);
}

// round 7
// speedup vs baseline: 3.7596x; 1.1209x over previous
#include <cuda_runtime.h>
#include <cuda_bf16.h>
#include <math.h>
#include <stdint.h>

#define T   2048
#define Dm  512
#define Np  32
#define Hd  2048
#define Kk  4
#define NHd 8
#define HDd 64
#define Sd  1024
#define Bd  2
#define D3  1536

#define AT_PAD 68
#define AT_REG (64 * AT_PAD)
#define SMEM_ATTN (3 * AT_REG * 4)

// HMMA tile constants: pitch 72 bf16 per row, 128 rows per tile
#define FP 72
#define FTILE (128 * FP)               // bf16 units per tile
#define SMEM_FFN (4 * FTILE * 2)       // bytes: 2 bufs x (A + B)

__device__ int   g_idx[T * Kk];
__device__ int   g_cnt[Np];
__device__ int   g_list[Np * T];
__device__ float g_pairs[T * Kk * Dm];
__device__ float g_nout[T * Dm];
__device__ float g_qkv[T * D3];
__device__ float g_attno[T * Dm];
__device__ float g_attnout[T * Dm];
__device__ __nv_bfloat16 g_x3[T * 2 * Dm];                 // [t][hi(512)|lo(512)]
__device__ __nv_bfloat16 g_nout3[T * 2 * Dm];
__device__ __nv_bfloat16 g_attno3[T * 2 * Dm];
__device__ __nv_bfloat16 g_W13[(size_t)Np * Hd * 2 * Dm];  // [n][h][Wh|Wl]
__device__ __nv_bfloat16 g_W23[(size_t)Np * Dm * 2 * Hd];  // [n][d][Wh|Wl]
__device__ __nv_bfloat16 g_Wqkv3[(size_t)D3 * 2 * Dm];     // [n][Wh(512)|Wl(512)]
__device__ __nv_bfloat16 g_Wo3[(size_t)Dm * 2 * Dm];
__device__ __nv_bfloat16 g_h3[(size_t)T * Kk * 2 * Hd];    // [pair][hh|hl]

__device__ __forceinline__ float gelu_f(float v) {
    float u = 0.7978845608028654f * (v + 0.044715f * v * v * v);
    return 0.5f * v * (1.0f + tanhf(u));
}

__device__ __forceinline__ uint32_t cvta_smem(const void* p) {
    uint32_t a;
    asm("{ .reg .u64 t; cvta.to.shared.u64 t, %1; cvt.u32.u64 %0, t; }" : "=r"(a) : "l"(p));
    return a;
}

__device__ __forceinline__ void mma_bf16(float c[4], uint32_t a0, uint32_t a1,
                                         uint32_t a2, uint32_t a3,
                                         uint32_t b0, uint32_t b1) {
    asm volatile(
        "mma.sync.aligned.m16n8k16.row.col.f32.bf16.bf16.f32 "
        "{%0,%1,%2,%3}, {%4,%5,%6,%7}, {%8,%9}, {%0,%1,%2,%3};"
        : "+f"(c[0]), "+f"(c[1]), "+f"(c[2]), "+f"(c[3])
        : "r"(a0), "r"(a1), "r"(a2), "r"(a3), "r"(b0), "r"(b1));
}

__device__ __forceinline__ void ldsm4(uint32_t r[4], uint32_t a) {
    asm volatile("ldmatrix.sync.aligned.m8n8.x4.shared.b16 {%0,%1,%2,%3}, [%4];"
        : "=r"(r[0]), "=r"(r[1]), "=r"(r[2]), "=r"(r[3]) : "r"(a));
}

// ---------------- router / list ----------------
__global__ void router_k(const float* __restrict__ x, const float* __restrict__ Wr,
                         const float* __restrict__ br) {
    int warp = threadIdx.x >> 5, lane = threadIdx.x & 31;
    int t = blockIdx.x * 8 + warp;
    const float* xp = x + (size_t)t * Dm + lane * 16;
    float4 xv[4];
#pragma unroll
    for (int i = 0; i < 4; i++) xv[i] = *(const float4*)(xp + i * 4);
    float lg[32];
#pragma unroll 1
    for (int n = 0; n < 32; n++) {
        const float* wp = Wr + n * Dm + lane * 16;
        float acc = 0.f;
#pragma unroll
        for (int i = 0; i < 4; i++) {
            float4 w = *(const float4*)(wp + i * 4);
            acc += xv[i].x * w.x + xv[i].y * w.y + xv[i].z * w.z + xv[i].w * w.w;
        }
#pragma unroll
        for (int o = 16; o; o >>= 1) acc += __shfl_xor_sync(0xffffffffu, acc, o);
        lg[n] = acc + br[n];
    }
    if (lane == 0) {
        unsigned used = 0;
        for (int k2 = 0; k2 < 4; k2++) {
            float best = -1e30f; int bi = 0;
            for (int n = 0; n < 32; n++)
                if (!((used >> n) & 1u) && lg[n] > best) { best = lg[n]; bi = n; }
            used |= 1u << bi;
            g_idx[t * 4 + k2] = bi;
        }
    }
}
__global__ void zero_k() { if (threadIdx.x < Np) g_cnt[threadIdx.x] = 0; }
__global__ void build_k() {
    int e = blockIdx.x * 256 + threadIdx.x;
    if (e >= T * Kk) return;
    int n = g_idx[e];
    int pos = atomicAdd(&g_cnt[n], 1);
    g_list[n * T + pos] = e;
}

// ---------------- bf16 split conversions ----------------
// [T x 512] fp32 -> [T][hi512|lo512] bf16
__global__ void conv3_k(const float* __restrict__ src, __nv_bfloat16* __restrict__ dst) {
    int i = blockIdx.x * 256 + threadIdx.x;
    int t = i >> 9, d = i & 511;
    float v = src[i];
    __nv_bfloat16 hi = __float2bfloat16(v);
    __nv_bfloat16 lo = __float2bfloat16(v - __bfloat162float(hi));
    dst[(size_t)t * 1024 + d] = hi;
    dst[(size_t)t * 1024 + 512 + d] = lo;
}
// W[n][Kd][Nd] fp32 -> W3[n][Nd][2*Kd] bf16 (hi|lo)  (transposing)
__global__ void convw_k(const float* __restrict__ W, __nv_bfloat16* __restrict__ W3,
                        int Kd, int Nd) {
    __shared__ float tile[32][33];
    int n = blockIdx.z, k0 = blockIdx.y * 32, c0 = blockIdx.x * 32;
    const float* Wn = W + (size_t)n * Kd * Nd;
#pragma unroll
    for (int i = 0; i < 32; i += 8)
        tile[threadIdx.y + i][threadIdx.x] = Wn[(size_t)(k0 + threadIdx.y + i) * Nd + c0 + threadIdx.x];
    __syncthreads();
    __nv_bfloat16* Wo = W3 + (size_t)n * Nd * 2 * Kd;
#pragma unroll
    for (int i = 0; i < 32; i += 8) {
        float v = tile[threadIdx.x][threadIdx.y + i];
        __nv_bfloat16 hi = __float2bfloat16(v);
        __nv_bfloat16 lo = __float2bfloat16(v - __bfloat162float(hi));
        size_t ro = (size_t)(c0 + threadIdx.y + i) * 2 * Kd + k0 + threadIdx.x;
        Wo[ro] = hi;
        Wo[ro + Kd] = lo;
    }
}
// dense W[N][K] fp32 -> W3[N][2K] (no transpose)
__global__ void convwd_k(const float* __restrict__ W, __nv_bfloat16* __restrict__ W3, int K) {
    int i = blockIdx.x * 256 + threadIdx.x;
    int n = i / K, k = i - n * K;
    float v = W[i];
    __nv_bfloat16 hi = __float2bfloat16(v);
    __nv_bfloat16 lo = __float2bfloat16(v - __bfloat162float(hi));
    W3[(size_t)n * 2 * K + k] = hi;
    W3[(size_t)n * 2 * K + K + k] = lo;
}

// ---------------- shared HMMA mainloop pieces ----------------
// computes one k64 chunk from smem buffers into acc, using ldmatrix
__device__ __forceinline__ void hmma_chunk(uint32_t smb_bytes_A, uint32_t smb_bytes_B,
                                           int warpM, int warpN, int rA, int kA,
                                           int rB, int kB, float acc[4][4][4]) {
#pragma unroll
    for (int kk = 0; kk < 4; kk++) {
        uint32_t af[4][4], bf[4][2];
#pragma unroll
        for (int mt = 0; mt < 4; mt++)
            ldsm4(af[mt], smb_bytes_A + (uint32_t)(((warpM + mt * 16 + rA) * FP + kk * 16 + kA) * 2));
#pragma unroll
        for (int nt2 = 0; nt2 < 2; nt2++) {
            uint32_t treg[4];
            ldsm4(treg, smb_bytes_B + (uint32_t)(((warpN + nt2 * 16 + rB) * FP + kk * 16 + kB) * 2));
            bf[2 * nt2][0] = treg[0]; bf[2 * nt2][1] = treg[1];
            bf[2 * nt2 + 1][0] = treg[2]; bf[2 * nt2 + 1][1] = treg[3];
        }
#pragma unroll
        for (int mt = 0; mt < 4; mt++)
#pragma unroll
            for (int nt = 0; nt < 4; nt++)
                mma_bf16(acc[mt][nt], af[mt][0], af[mt][1], af[mt][2], af[mt][3],
                         bf[nt][0], bf[nt][1]);
    }
}

// ---------------- FFN pass 1: h = gelu(x @ W1 + b1) ----------------
__global__ __launch_bounds__(256)
void ffn1_mma_k(const float* __restrict__ b1) {
    int n = blockIdx.z, mt0 = blockIdx.y, nb = blockIdx.x * 128;
    int cnt = g_cnt[n];
    int base = mt0 * 128;
    if (base >= cnt) return;

    extern __shared__ __align__(16) __nv_bfloat16 sm[];
    __shared__ int es[128];
    int tid = threadIdx.x, wid = tid >> 5, lane = tid & 31;
    if (tid < 128) es[tid] = (base + tid < cnt) ? g_list[n * T + base + tid] : -1;
    __syncthreads();

    int hr = tid >> 1, half = tid & 1;
    int e_row = es[hr];
    const __nv_bfloat16* arow = (e_row >= 0) ? (g_x3 + (size_t)(e_row >> 2) * 1024) : 0;
    const __nv_bfloat16* brow = g_W13 + ((size_t)n * Hd + nb + hr) * 1024;
    int sto = hr * FP + half * 32;

    float acc[4][4][4];
#pragma unroll
    for (int i = 0; i < 4; i++)
#pragma unroll
        for (int j = 0; j < 4; j++)
#pragma unroll
            for (int k = 0; k < 4; k++) acc[i][j][k] = 0.f;

    int g = lane >> 2, t2 = (lane & 3) * 2;
    int warpM = (wid >> 2) * 64, warpN = (wid & 3) * 32;
    int rA = ((lane >> 3) & 1) * 8 + (lane & 7);
    int kA = (lane >> 4) * 8;
    int rB = (lane & 7) + (lane >> 4) * 8;
    int kB = ((lane >> 3) & 1) * 8;
    uint32_t smb = cvta_smem(sm);

    const int NCH = 24;
    uint4 ra[4], rb[4];
    if (arow) {
#pragma unroll
        for (int i = 0; i < 4; i++) ra[i] = *(const uint4*)(arow + half * 32 + i * 8);
    } else {
#pragma unroll
        for (int i = 0; i < 4; i++) ra[i] = make_uint4(0, 0, 0, 0);
    }
#pragma unroll
    for (int i = 0; i < 4; i++) rb[i] = *(const uint4*)(brow + half * 32 + i * 8);
#pragma unroll
    for (int i = 0; i < 4; i++) {
        *(uint4*)(sm + sto + i * 8) = ra[i];
        *(uint4*)(sm + FTILE + sto + i * 8) = rb[i];
    }
    __syncthreads();

#pragma unroll 1
    for (int c = 0; c < NCH; c++) {
        int buf = c & 1;
        if (c + 1 < NCH) {
            int c1 = c + 1;
            int kc = c1 & 7;
            int sA = (c1 < 16) ? 0 : 512;
            int sB = (c1 >= 8 && c1 < 16) ? 512 : 0;
            if (arow) {
                const __nv_bfloat16* ap = arow + sA + kc * 64 + half * 32;
#pragma unroll
                for (int i = 0; i < 4; i++) ra[i] = *(const uint4*)(ap + i * 8);
            }
            const __nv_bfloat16* bp = brow + sB + kc * 64 + half * 32;
#pragma unroll
            for (int i = 0; i < 4; i++) rb[i] = *(const uint4*)(bp + i * 8);
        }
        uint32_t baseA = smb + (uint32_t)(buf * 2 * FTILE * 2);
        hmma_chunk(baseA, baseA + FTILE * 2, warpM, warpN, rA, kA, rB, kB, acc);
        if (c + 1 < NCH) {
            __nv_bfloat16* d = sm + ((c + 1) & 1) * 2 * FTILE;
#pragma unroll
            for (int i = 0; i < 4; i++) {
                *(uint4*)(d + sto + i * 8) = ra[i];
                *(uint4*)(d + FTILE + sto + i * 8) = rb[i];
            }
        }
        __syncthreads();
    }

#pragma unroll
    for (int mt = 0; mt < 4; mt++) {
#pragma unroll
        for (int rr = 0; rr < 2; rr++) {
            int row = warpM + mt * 16 + g + rr * 8;
            int er = es[row];
            if (er < 0) continue;
            __nv_bfloat16* hp = g_h3 + (size_t)er * 4096;
#pragma unroll
            for (int nt = 0; nt < 4; nt++) {
                int col = nb + warpN + nt * 8 + t2;
                float v0 = gelu_f(acc[mt][nt][rr * 2 + 0] + b1[(size_t)n * Hd + col]);
                float v1 = gelu_f(acc[mt][nt][rr * 2 + 1] + b1[(size_t)n * Hd + col + 1]);
                __nv_bfloat16 h0 = __float2bfloat16(v0), h1 = __float2bfloat16(v1);
                __nv_bfloat16 l0 = __float2bfloat16(v0 - __bfloat162float(h0));
                __nv_bfloat16 l1 = __float2bfloat16(v1 - __bfloat162float(h1));
                uint32_t hp2 = (uint32_t)__bfloat16_as_ushort(h0) | ((uint32_t)__bfloat16_as_ushort(h1) << 16);
                uint32_t lp2 = (uint32_t)__bfloat16_as_ushort(l0) | ((uint32_t)__bfloat16_as_ushort(l1) << 16);
                *(uint32_t*)(hp + col) = hp2;
                *(uint32_t*)(hp + 2048 + col) = lp2;
            }
        }
    }
}

// ---------------- FFN pass 2: out = h @ W2 + b2 ----------------
__global__ __launch_bounds__(256)
void ffn2_mma_k(const float* __restrict__ b2) {
    int n = blockIdx.z, mt0 = blockIdx.y, nb = blockIdx.x * 128;
    int cnt = g_cnt[n];
    int base = mt0 * 128;
    if (base >= cnt) return;

    extern __shared__ __align__(16) __nv_bfloat16 sm[];
    __shared__ int es[128];
    int tid = threadIdx.x, wid = tid >> 5, lane = tid & 31;
    if (tid < 128) es[tid] = (base + tid < cnt) ? g_list[n * T + base + tid] : -1;
    __syncthreads();

    int hr = tid >> 1, half = tid & 1;
    int e_row = es[hr];
    const __nv_bfloat16* arow = (e_row >= 0) ? (g_h3 + (size_t)e_row * 4096) : 0;
    const __nv_bfloat16* brow = g_W23 + ((size_t)n * Dm + nb + hr) * 4096;
    int sto = hr * FP + half * 32;

    float acc[4][4][4];
#pragma unroll
    for (int i = 0; i < 4; i++)
#pragma unroll
        for (int j = 0; j < 4; j++)
#pragma unroll
            for (int k = 0; k < 4; k++) acc[i][j][k] = 0.f;

    int g = lane >> 2, t2 = (lane & 3) * 2;
    int warpM = (wid >> 2) * 64, warpN = (wid & 3) * 32;
    int rA = ((lane >> 3) & 1) * 8 + (lane & 7);
    int kA = (lane >> 4) * 8;
    int rB = (lane & 7) + (lane >> 4) * 8;
    int kB = ((lane >> 3) & 1) * 8;
    uint32_t smb = cvta_smem(sm);

    const int NCH = 96;
    uint4 ra[4], rb[4];
    if (arow) {
#pragma unroll
        for (int i = 0; i < 4; i++) ra[i] = *(const uint4*)(arow + half * 32 + i * 8);
    } else {
#pragma unroll
        for (int i = 0; i < 4; i++) ra[i] = make_uint4(0, 0, 0, 0);
    }
#pragma unroll
    for (int i = 0; i < 4; i++) rb[i] = *(const uint4*)(brow + half * 32 + i * 8);
#pragma unroll
    for (int i = 0; i < 4; i++) {
        *(uint4*)(sm + sto + i * 8) = ra[i];
        *(uint4*)(sm + FTILE + sto + i * 8) = rb[i];
    }
    __syncthreads();

#pragma unroll 1
    for (int c = 0; c < NCH; c++) {
        int buf = c & 1;
        if (c + 1 < NCH) {
            int c1 = c + 1;
            int kc = c1 & 31;
            int sA = (c1 < 64) ? 0 : 2048;
            int sB = (c1 >= 32 && c1 < 64) ? 2048 : 0;
            if (arow) {
                const __nv_bfloat16* ap = arow + sA + kc * 64 + half * 32;
#pragma unroll
                for (int i = 0; i < 4; i++) ra[i] = *(const uint4*)(ap + i * 8);
            }
            const __nv_bfloat16* bp = brow + sB + kc * 64 + half * 32;
#pragma unroll
            for (int i = 0; i < 4; i++) rb[i] = *(const uint4*)(bp + i * 8);
        }
        uint32_t baseA = smb + (uint32_t)(buf * 2 * FTILE * 2);
        hmma_chunk(baseA, baseA + FTILE * 2, warpM, warpN, rA, kA, rB, kB, acc);
        if (c + 1 < NCH) {
            __nv_bfloat16* d = sm + ((c + 1) & 1) * 2 * FTILE;
#pragma unroll
            for (int i = 0; i < 4; i++) {
                *(uint4*)(d + sto + i * 8) = ra[i];
                *(uint4*)(d + FTILE + sto + i * 8) = rb[i];
            }
        }
        __syncthreads();
    }

#pragma unroll
    for (int mt = 0; mt < 4; mt++) {
#pragma unroll
        for (int rr = 0; rr < 2; rr++) {
            int row = warpM + mt * 16 + g + rr * 8;
            int er = es[row];
            if (er < 0) continue;
            float* op = g_pairs + (size_t)er * Dm;
#pragma unroll
            for (int nt = 0; nt < 4; nt++) {
                int col = nb + warpN + nt * 8 + t2;
                float2 o;
                o.x = acc[mt][nt][rr * 2 + 0] + b2[(size_t)n * Dm + col];
                o.y = acc[mt][nt][rr * 2 + 1] + b2[(size_t)n * Dm + col + 1];
                *(float2*)(op + col) = o;
            }
        }
    }
}

// ---------------- dense HMMA GEMM: C[M,Nc] = A @ W^T + bias ----------------
// A3: [M][2*Kd] bf16 hi|lo. W3: [Nc][2*Kd] bf16 hi|lo. grid (Nc/128, M/128), 256 thr.
__global__ __launch_bounds__(256)
void gemm_mma_k(const __nv_bfloat16* __restrict__ A3, const __nv_bfloat16* __restrict__ W3,
                const float* __restrict__ bias, float* __restrict__ C, int Nc, int Kd) {
    int nb = blockIdx.x * 128, mg = blockIdx.y * 128;
    extern __shared__ __align__(16) __nv_bfloat16 sm[];
    int tid = threadIdx.x, wid = tid >> 5, lane = tid & 31;

    int hr = tid >> 1, half = tid & 1;
    const __nv_bfloat16* arow = A3 + (size_t)(mg + hr) * 2 * Kd;
    const __nv_bfloat16* brow = W3 + (size_t)(nb + hr) * 2 * Kd;
    int sto = hr * FP + half * 32;

    float acc[4][4][4];
#pragma unroll
    for (int i = 0; i < 4; i++)
#pragma unroll
        for (int j = 0; j < 4; j++)
#pragma unroll
            for (int k = 0; k < 4; k++) acc[i][j][k] = 0.f;

    int g = lane >> 2, t2 = (lane & 3) * 2;
    int warpM = (wid >> 2) * 64, warpN = (wid & 3) * 32;
    int rA = ((lane >> 3) & 1) * 8 + (lane & 7);
    int kA = (lane >> 4) * 8;
    int rB = (lane & 7) + (lane >> 4) * 8;
    int kB = ((lane >> 3) & 1) * 8;
    uint32_t smb = cvta_smem(sm);

    int cpseg = Kd >> 6;
    int NCH = 3 * cpseg;
    uint4 ra[4], rb[4];
#pragma unroll
    for (int i = 0; i < 4; i++) {
        ra[i] = *(const uint4*)(arow + half * 32 + i * 8);
        rb[i] = *(const uint4*)(brow + half * 32 + i * 8);
    }
#pragma unroll
    for (int i = 0; i < 4; i++) {
        *(uint4*)(sm + sto + i * 8) = ra[i];
        *(uint4*)(sm + FTILE + sto + i * 8) = rb[i];
    }
    __syncthreads();

#pragma unroll 1
    for (int c = 0; c < NCH; c++) {
        int buf = c & 1;
        if (c + 1 < NCH) {
            int c1 = c + 1;
            int seg = c1 / cpseg;
            int kc = c1 - seg * cpseg;
            int sA = (seg == 2) ? Kd : 0;
            int sB = (seg == 1) ? Kd : 0;
            const __nv_bfloat16* ap = arow + sA + kc * 64 + half * 32;
            const __nv_bfloat16* bp = brow + sB + kc * 64 + half * 32;
#pragma unroll
            for (int i = 0; i < 4; i++) {
                ra[i] = *(const uint4*)(ap + i * 8);
                rb[i] = *(const uint4*)(bp + i * 8);
            }
        }
        uint32_t baseA = smb + (uint32_t)(buf * 2 * FTILE * 2);
        hmma_chunk(baseA, baseA + FTILE * 2, warpM, warpN, rA, kA, rB, kB, acc);
        if (c + 1 < NCH) {
            __nv_bfloat16* d = sm + ((c + 1) & 1) * 2 * FTILE;
#pragma unroll
            for (int i = 0; i < 4; i++) {
                *(uint4*)(d + sto + i * 8) = ra[i];
                *(uint4*)(d + FTILE + sto + i * 8) = rb[i];
            }
        }
        __syncthreads();
    }

#pragma unroll
    for (int mt = 0; mt < 4; mt++) {
#pragma unroll
        for (int rr = 0; rr < 2; rr++) {
            int row = mg + warpM + mt * 16 + g + rr * 8;
            float* op = C + (size_t)row * Nc;
#pragma unroll
            for (int nt = 0; nt < 4; nt++) {
                int col = nb + warpN + nt * 8 + t2;
                float2 o;
                o.x = acc[mt][nt][rr * 2 + 0] + bias[col];
                o.y = acc[mt][nt][rr * 2 + 1] + bias[col + 1];
                *(float2*)(op + col) = o;
            }
        }
    }
}

// ---------------- mean over k ----------------
__global__ void reduce_k() {
    int id = blockIdx.x * 256 + threadIdx.x;
    if (id >= T * Dm / 4) return;
    int t = id >> 7, c4 = (id & 127) << 2;
    float4 s = make_float4(0.f, 0.f, 0.f, 0.f);
#pragma unroll
    for (int k2 = 0; k2 < 4; k2++) {
        float4 v = *(const float4*)&g_pairs[(size_t)(t * 4 + k2) * Dm + c4];
        s.x += v.x; s.y += v.y; s.z += v.z; s.w += v.w;
    }
    s.x *= 0.25f; s.y *= 0.25f; s.z *= 0.25f; s.w *= 0.25f;
    *(float4*)&g_nout[(size_t)t * Dm + c4] = s;
}

// ---------------- attention (flash, q-tile 64) ----------------
__global__ __launch_bounds__(256)
void attn2_k() {
    extern __shared__ float smf[];
    float* Qs  = smf;
    float* KPs = smf + AT_REG;
    float* Vs  = smf + 2 * AT_REG;
    int q0 = blockIdx.x * 64, h = blockIdx.y, b = blockIdx.z;
    int tid = threadIdx.x, lane = tid & 31, w = tid >> 5;
    int qr = w * 8;
    {
        int r = tid >> 2, c0 = (tid & 3) * 16;
        const float* qp = g_qkv + (size_t)(b * Sd + q0 + r) * D3 + h * HDd + c0;
#pragma unroll
        for (int i = 0; i < 4; i++) {
            float4 v = *(const float4*)(qp + i * 4);
            Qs[(c0 + i * 4 + 0) * AT_PAD + r] = v.x * 0.125f;
            Qs[(c0 + i * 4 + 1) * AT_PAD + r] = v.y * 0.125f;
            Qs[(c0 + i * 4 + 2) * AT_PAD + r] = v.z * 0.125f;
            Qs[(c0 + i * 4 + 3) * AT_PAD + r] = v.w * 0.125f;
        }
    }
    float m[8], l[8], o0[8], o1[8];
#pragma unroll
    for (int r = 0; r < 8; r++) { m[r] = -1e30f; l[r] = 0.f; o0[r] = 0.f; o1[r] = 0.f; }
#pragma unroll 1
    for (int j0 = 0; j0 < Sd; j0 += 64) {
        __syncthreads();
        {
            int r = tid >> 2, c0 = (tid & 3) * 16;
            const float* kp = g_qkv + (size_t)(b * Sd + j0 + r) * D3 + Dm + h * HDd + c0;
            const float* vp = kp + Dm;
#pragma unroll
            for (int i = 0; i < 4; i++) {
                float4 kv = *(const float4*)(kp + i * 4);
                KPs[(c0 + i * 4 + 0) * AT_PAD + r] = kv.x;
                KPs[(c0 + i * 4 + 1) * AT_PAD + r] = kv.y;
                KPs[(c0 + i * 4 + 2) * AT_PAD + r] = kv.z;
                KPs[(c0 + i * 4 + 3) * AT_PAD + r] = kv.w;
                float4 vv = *(const float4*)(vp + i * 4);
                Vs[(c0 + i * 4 + 0) * AT_PAD + r] = vv.x;
                Vs[(c0 + i * 4 + 1) * AT_PAD + r] = vv.y;
                Vs[(c0 + i * 4 + 2) * AT_PAD + r] = vv.z;
                Vs[(c0 + i * 4 + 3) * AT_PAD + r] = vv.w;
            }
        }
        __syncthreads();
        float s[8][2];
#pragma unroll
        for (int r = 0; r < 8; r++) { s[r][0] = 0.f; s[r][1] = 0.f; }
#pragma unroll 8
        for (int d = 0; d < 64; d++) {
            float4 qa = *(const float4*)&Qs[d * AT_PAD + qr];
            float4 qb = *(const float4*)&Qs[d * AT_PAD + qr + 4];
            float2 kk = *(const float2*)&KPs[d * AT_PAD + 2 * lane];
            s[0][0] += qa.x * kk.x; s[0][1] += qa.x * kk.y;
            s[1][0] += qa.y * kk.x; s[1][1] += qa.y * kk.y;
            s[2][0] += qa.z * kk.x; s[2][1] += qa.z * kk.y;
            s[3][0] += qa.w * kk.x; s[3][1] += qa.w * kk.y;
            s[4][0] += qb.x * kk.x; s[4][1] += qb.x * kk.y;
            s[5][0] += qb.y * kk.x; s[5][1] += qb.y * kk.y;
            s[6][0] += qb.z * kk.x; s[6][1] += qb.z * kk.y;
            s[7][0] += qb.w * kk.x; s[7][1] += qb.w * kk.y;
        }
#pragma unroll
        for (int r = 0; r < 8; r++) {
            float tmax = fmaxf(s[r][0], s[r][1]);
#pragma unroll
            for (int o = 16; o; o >>= 1) tmax = fmaxf(tmax, __shfl_xor_sync(0xffffffffu, tmax, o));
            float mn = fmaxf(m[r], tmax);
            float corr = __expf(m[r] - mn);
            float p0 = __expf(s[r][0] - mn);
            float p1 = __expf(s[r][1] - mn);
            float rs = p0 + p1;
#pragma unroll
            for (int o = 16; o; o >>= 1) rs += __shfl_xor_sync(0xffffffffu, rs, o);
            l[r] = l[r] * corr + rs;
            m[r] = mn;
            o0[r] *= corr; o1[r] *= corr;
            s[r][0] = p0; s[r][1] = p1;
        }
        __syncthreads();
#pragma unroll
        for (int r = 0; r < 8; r++)
            *(float2*)&KPs[(qr + r) * AT_PAD + 2 * lane] = make_float2(s[r][0], s[r][1]);
        __syncthreads();
        const float* vr0 = &Vs[lane * AT_PAD];
        const float* vr1 = &Vs[(lane + 32) * AT_PAD];
#pragma unroll 4
        for (int k4 = 0; k4 < 16; k4++) {
            float4 v0 = *(const float4*)(vr0 + 4 * k4);
            float4 v1 = *(const float4*)(vr1 + 4 * k4);
#pragma unroll
            for (int r = 0; r < 8; r++) {
                float4 p = *(const float4*)&KPs[(qr + r) * AT_PAD + 4 * k4];
                o0[r] += p.x * v0.x + p.y * v0.y + p.z * v0.z + p.w * v0.w;
                o1[r] += p.x * v1.x + p.y * v1.y + p.z * v1.z + p.w * v1.w;
            }
        }
    }
#pragma unroll
    for (int r = 0; r < 8; r++) {
        float inv = 1.0f / l[r];
        int t = b * Sd + q0 + qr + r;
        g_attno[(size_t)t * Dm + h * HDd + lane] = o0[r] * inv;
        g_attno[(size_t)t * Dm + h * HDd + lane + 32] = o1[r] * inv;
    }
}

// ---------------- fused dual LN ----------------
__global__ void ln_k(const float* __restrict__ x,
                     const float* __restrict__ ln1w, const float* __restrict__ ln1b,
                     const float* __restrict__ ln2w, const float* __restrict__ ln2b,
                     float* __restrict__ out) {
    int t = blockIdx.x, tid = threadIdx.x;
    __shared__ float r1[8], r2[8];
    __shared__ float mu_s, rs_s;
    size_t off = (size_t)t * Dm;
    float a0 = x[off + tid] + g_attnout[off + tid];
    float a1 = x[off + 256 + tid] + g_attnout[off + 256 + tid];
    float s = a0 + a1, ss = a0 * a0 + a1 * a1;
#pragma unroll
    for (int o = 16; o; o >>= 1) {
        s += __shfl_xor_sync(0xffffffffu, s, o);
        ss += __shfl_xor_sync(0xffffffffu, ss, o);
    }
    if ((tid & 31) == 0) { r1[tid >> 5] = s; r2[tid >> 5] = ss; }
    __syncthreads();
    if (tid == 0) {
        float S = 0.f, SS = 0.f;
#pragma unroll
        for (int i = 0; i < 8; i++) { S += r1[i]; SS += r2[i]; }
        float mu = S * (1.0f / 512.0f);
        mu_s = mu;
        rs_s = rsqrtf(SS * (1.0f / 512.0f) - mu * mu + 1e-5f);
    }
    __syncthreads();
    float mu = mu_s, rs = rs_s;
    float z0 = (a0 - mu) * rs * ln1w[tid] + ln1b[tid] + g_nout[off + tid];
    float z1 = (a1 - mu) * rs * ln1w[256 + tid] + ln1b[256 + tid] + g_nout[off + 256 + tid];
    s = z0 + z1; ss = z0 * z0 + z1 * z1;
#pragma unroll
    for (int o = 16; o; o >>= 1) {
        s += __shfl_xor_sync(0xffffffffu, s, o);
        ss += __shfl_xor_sync(0xffffffffu, ss, o);
    }
    __syncthreads();
    if ((tid & 31) == 0) { r1[tid >> 5] = s; r2[tid >> 5] = ss; }
    __syncthreads();
    if (tid == 0) {
        float S = 0.f, SS = 0.f;
#pragma unroll
        for (int i = 0; i < 8; i++) { S += r1[i]; SS += r2[i]; }
        float mu2 = S * (1.0f / 512.0f);
        mu_s = mu2;
        rs_s = rsqrtf(SS * (1.0f / 512.0f) - mu2 * mu2 + 1e-5f);
    }
    __syncthreads();
    mu = mu_s; rs = rs_s;
    out[off + tid] = (z0 - mu) * rs * ln2w[tid] + ln2b[tid];
    out[off + 256 + tid] = (z1 - mu) * rs * ln2w[256 + tid] + ln2b[256 + tid];
}

// ---------------- launcher ----------------
extern "C" void kernel_launch(void* const* d_in, const int* in_sizes, int n_in,
                              void* d_out, int out_size) {
    const float* x    = (const float*)d_in[0];
    const float* Wr   = (const float*)d_in[1];
    const float* br   = (const float*)d_in[2];
    const float* W1   = (const float*)d_in[3];
    const float* b1   = (const float*)d_in[4];
    const float* W2   = (const float*)d_in[5];
    const float* b2   = (const float*)d_in[6];
    const float* Wqkv = (const float*)d_in[7];
    const float* bqkv = (const float*)d_in[8];
    const float* Wo   = (const float*)d_in[9];
    const float* bo   = (const float*)d_in[10];
    const float* ln1w = (const float*)d_in[11];
    const float* ln1b = (const float*)d_in[12];
    const float* ln2w = (const float*)d_in[13];
    const float* ln2b = (const float*)d_in[14];
    float* out = (float*)d_out;

    float *p_nout, *p_qkv, *p_attno, *p_attnout;
    __nv_bfloat16 *p_x3, *p_w13, *p_w23, *p_wqkv3, *p_wo3, *p_nout3, *p_attno3;
    cudaGetSymbolAddress((void**)&p_nout, g_nout);
    cudaGetSymbolAddress((void**)&p_qkv, g_qkv);
    cudaGetSymbolAddress((void**)&p_attno, g_attno);
    cudaGetSymbolAddress((void**)&p_attnout, g_attnout);
    cudaGetSymbolAddress((void**)&p_x3, g_x3);
    cudaGetSymbolAddress((void**)&p_w13, g_W13);
    cudaGetSymbolAddress((void**)&p_w23, g_W23);
    cudaGetSymbolAddress((void**)&p_wqkv3, g_Wqkv3);
    cudaGetSymbolAddress((void**)&p_wo3, g_Wo3);
    cudaGetSymbolAddress((void**)&p_nout3, g_nout3);
    cudaGetSymbolAddress((void**)&p_attno3, g_attno3);

    static int attr_set = 0;
    if (!attr_set) {
        cudaFuncSetAttribute(attn2_k, cudaFuncAttributeMaxDynamicSharedMemorySize, SMEM_ATTN);
        cudaFuncSetAttribute(ffn1_mma_k, cudaFuncAttributeMaxDynamicSharedMemorySize, SMEM_FFN);
        cudaFuncSetAttribute(ffn2_mma_k, cudaFuncAttributeMaxDynamicSharedMemorySize, SMEM_FFN);
        cudaFuncSetAttribute(gemm_mma_k, cudaFuncAttributeMaxDynamicSharedMemorySize, SMEM_FFN);
        attr_set = 1;
    }

    // router + list build
    router_k<<<T / 8, 256>>>(x, Wr, br);
    zero_k<<<1, 32>>>();
    build_k<<<(T * Kk + 255) / 256, 256>>>();

    // bf16 hi/lo splits
    conv3_k<<<T * Dm / 256, 256>>>(x, p_x3);
    convw_k<<<dim3(Hd / 32, Dm / 32, Np), dim3(32, 8)>>>(W1, p_w13, Dm, Hd);
    convw_k<<<dim3(Dm / 32, Hd / 32, Np), dim3(32, 8)>>>(W2, p_w23, Hd, Dm);
    convwd_k<<<D3 * Dm / 256, 256>>>(Wqkv, p_wqkv3, Dm);
    convwd_k<<<Dm * Dm / 256, 256>>>(Wo, p_wo3, Dm);

    // sparse FFN on tensor cores
    ffn1_mma_k<<<dim3(16, 16, 32), 256, SMEM_FFN>>>(b1);
    ffn2_mma_k<<<dim3(4, 16, 32), 256, SMEM_FFN>>>(b2);
    reduce_k<<<(T * Dm / 4 + 255) / 256, 256>>>();
    conv3_k<<<T * Dm / 256, 256>>>(p_nout, p_nout3);

    // attention (HMMA projections + fp32 flash core)
    gemm_mma_k<<<dim3(D3 / 128, T / 128), 256, SMEM_FFN>>>(p_nout3, p_wqkv3, bqkv, p_qkv, D3, Dm);
    attn2_k<<<dim3(Sd / 64, NHd, Bd), 256, SMEM_ATTN>>>();
    conv3_k<<<T * Dm / 256, 256>>>(p_attno, p_attno3);
    gemm_mma_k<<<dim3(Dm / 128, T / 128), 256, SMEM_FFN>>>(p_attno3, p_wo3, bo, p_attnout, Dm, Dm);

    // epilogue
    ln_k<<<T, 256>>>(x, ln1w, ln1b, ln2w, ln2b, out);
}